// round 1
// baseline (speedup 1.0000x reference)
#include <cuda_runtime.h>
#include <cuda_bf16.h>
#include <math.h>

// Problem constants: B=4, N=4096, C=1024, H=16, D=64
#define BATCH 4
#define SEQ   4096
#define CH    1024
#define HEADS 16
#define HD    64
#define ROWS  (BATCH*SEQ)        // 16384
#define QKVC  (3*CH)             // 3072
#define BH    (BATCH*HEADS)      // 64

// ---------------- scratch (device globals: allocation-free) ----------------
__device__ float g_qkv [(size_t)ROWS * QKVC];   // 201 MB: qkv projection (elu+1 applied to q,k)
__device__ float g_kv  [(size_t)BH * HD * HD];  // 1 MB: per-head kv = k^T v
__device__ float g_sumk[(size_t)BH * HD];       // sum over n of k
__device__ float g_y   [(size_t)ROWS * CH];     // 64 MB: merged-head attention output

// ---------------- SGEMM: C = A(MxK) @ B(KxN) [+epilogue] -------------------
// 128x128 block tile, BK=16, 256 threads, 8x8 per-thread microtile.
// MODE 0: none. MODE 1: elu+1 on columns < 2048 (q,k feature map). MODE 2: +bias.
template <int MODE>
__global__ __launch_bounds__(256, 2)
void sgemm_kernel(const float* __restrict__ A, const float* __restrict__ B,
                  const float* __restrict__ bias, float* __restrict__ C,
                  int M, int N, int K)
{
    const int BM = 128, BN = 128, BK = 16, TM = 8, TN = 8;
    __shared__ float As[BK][BM];
    __shared__ float Bs[BK][BN];

    const int tid  = threadIdx.x;          // 0..255
    const int brow = blockIdx.y;           // M tile
    const int bcol = blockIdx.x;           // N tile
    const int trow = tid / 16;             // 0..15  (M dir)
    const int tcol = tid % 16;             // 0..15  (N dir)

    float acc[TM][TN];
    #pragma unroll
    for (int i = 0; i < TM; i++)
        #pragma unroll
        for (int j = 0; j < TN; j++) acc[i][j] = 0.f;

    // A tile loads: 128x16 floats = 512 float4, 2 per thread
    const int aRow  = tid / 4;             // 0..63 (+64)
    const int aCol4 = tid % 4;             // float4 col within 16
    // B tile loads: 16x128 floats = 512 float4, 2 per thread
    const int bRow  = tid / 32;            // 0..7 (+8)
    const int bCol4 = tid % 32;            // float4 col within 128

    const float* Aptr = A + (size_t)brow * BM * K;
    const float* Bptr = B + (size_t)bcol * BN;

    for (int k0 = 0; k0 < K; k0 += BK) {
        #pragma unroll
        for (int i = 0; i < 2; i++) {
            int r = aRow + i * 64;
            float4 t = *(const float4*)(Aptr + (size_t)r * K + k0 + aCol4 * 4);
            As[aCol4 * 4 + 0][r] = t.x;
            As[aCol4 * 4 + 1][r] = t.y;
            As[aCol4 * 4 + 2][r] = t.z;
            As[aCol4 * 4 + 3][r] = t.w;
        }
        #pragma unroll
        for (int i = 0; i < 2; i++) {
            int r = bRow + i * 8;
            *(float4*)&Bs[r][bCol4 * 4] =
                *(const float4*)(Bptr + (size_t)(k0 + r) * N + bCol4 * 4);
        }
        __syncthreads();

        #pragma unroll
        for (int kk = 0; kk < BK; kk++) {
            float aReg[TM], bReg[TN];
            #pragma unroll
            for (int i = 0; i < TM; i++) aReg[i] = As[kk][trow * TM + i];
            #pragma unroll
            for (int j = 0; j < TN; j++) bReg[j] = Bs[kk][tcol * TN + j];
            #pragma unroll
            for (int i = 0; i < TM; i++)
                #pragma unroll
                for (int j = 0; j < TN; j++)
                    acc[i][j] += aReg[i] * bReg[j];
        }
        __syncthreads();
    }

    const int cRow0 = brow * BM + trow * TM;
    const int cCol0 = bcol * BN + tcol * TN;
    #pragma unroll
    for (int i = 0; i < TM; i++) {
        #pragma unroll
        for (int j = 0; j < TN; j += 4) {
            float v[4];
            #pragma unroll
            for (int jj = 0; jj < 4; jj++) {
                float x = acc[i][j + jj];
                int col = cCol0 + j + jj;
                if (MODE == 1) {
                    // elu(x)+1 = x+1 (x>0) else exp(x); only on q,k columns
                    if (col < 2 * CH) x = (x > 0.f) ? (x + 1.f) : expf(x);
                } else if (MODE == 2) {
                    x += bias[col];
                }
                v[jj] = x;
            }
            *(float4*)(C + (size_t)(cRow0 + i) * N + cCol0 + j) =
                make_float4(v[0], v[1], v[2], v[3]);
        }
    }
}

// ---------------- kv = sum_n k[n,d]*v[n,e] and sumk[d] ---------------------
// one block per (b,h), 256 threads, each owns a 4x4 patch of the 64x64 kv.
__global__ __launch_bounds__(256)
void kv_kernel()
{
    const int bh = blockIdx.x;            // 0..63
    const int b  = bh / HEADS;
    const int h  = bh % HEADS;

    __shared__ float ks[32][HD];
    __shared__ float vs[32][HD];

    const int tid = threadIdx.x;
    const int e0  = (tid % 16) * 4;
    const int d0  = (tid / 16) * 4;

    float acc[4][4] = {};
    float sacc[4]   = {0.f, 0.f, 0.f, 0.f};

    const float* base = g_qkv + (size_t)b * SEQ * QKVC + h * HD;

    for (int n0 = 0; n0 < SEQ; n0 += 32) {
        #pragma unroll
        for (int i = 0; i < 2; i++) {
            int idx = tid + i * 256;       // 0..511
            int r   = idx / 16;
            int c4  = idx % 16;
            const float* rowp = base + (size_t)(n0 + r) * QKVC;
            *(float4*)&ks[r][c4 * 4] = *(const float4*)(rowp + CH     + c4 * 4);
            *(float4*)&vs[r][c4 * 4] = *(const float4*)(rowp + 2 * CH + c4 * 4);
        }
        __syncthreads();

        #pragma unroll 4
        for (int nn = 0; nn < 32; nn++) {
            float kr[4], vr[4];
            #pragma unroll
            for (int i = 0; i < 4; i++) kr[i] = ks[nn][d0 + i];
            #pragma unroll
            for (int j = 0; j < 4; j++) vr[j] = vs[nn][e0 + j];
            #pragma unroll
            for (int i = 0; i < 4; i++)
                #pragma unroll
                for (int j = 0; j < 4; j++)
                    acc[i][j] += kr[i] * vr[j];
            if (e0 == 0) {
                #pragma unroll
                for (int i = 0; i < 4; i++) sacc[i] += kr[i];
            }
        }
        __syncthreads();
    }

    float* kvp = g_kv + (size_t)bh * HD * HD;
    #pragma unroll
    for (int i = 0; i < 4; i++)
        *(float4*)&kvp[(d0 + i) * HD + e0] =
            make_float4(acc[i][0], acc[i][1], acc[i][2], acc[i][3]);
    if (e0 == 0) {
        #pragma unroll
        for (int i = 0; i < 4; i++) g_sumk[bh * HD + d0 + i] = sacc[i];
    }
}

// ---------------- y[n,e] = (q[n,:]·kv[:,e]) / (q[n,:]·sumk) ----------------
// grid (SEQ/128, BH), 128 threads, one n-row per thread; kv tile in smem.
__global__ __launch_bounds__(128)
void y_kernel()
{
    const int bh  = blockIdx.y;
    const int b   = bh / HEADS;
    const int h   = bh % HEADS;
    const int tid = threadIdx.x;
    const int n   = blockIdx.x * 128 + tid;

    __shared__ float kvs[HD][HD];
    __shared__ float sks[HD];

    const float* kvp = g_kv + (size_t)bh * HD * HD;
    for (int i = tid; i < HD * HD / 4; i += 128)
        ((float4*)kvs)[i] = ((const float4*)kvp)[i];
    if (tid < HD) sks[tid] = g_sumk[bh * HD + tid];
    __syncthreads();

    const float* qrow = g_qkv + ((size_t)b * SEQ + n) * QKVC + h * HD; // q at col 0
    float q[HD];
    #pragma unroll
    for (int d = 0; d < HD; d += 4) {
        float4 t = *(const float4*)(qrow + d);
        q[d] = t.x; q[d + 1] = t.y; q[d + 2] = t.z; q[d + 3] = t.w;
    }

    float denom = 0.f;
    #pragma unroll
    for (int d = 0; d < HD; d++) denom += q[d] * sks[d];
    const float inv = 1.0f / denom;   // q,k strictly positive -> denom > 0

    float* yrow = g_y + ((size_t)b * SEQ + n) * CH + h * HD;
    #pragma unroll 4
    for (int e = 0; e < HD; e += 4) {
        float a0 = 0.f, a1 = 0.f, a2 = 0.f, a3 = 0.f;
        #pragma unroll
        for (int d = 0; d < HD; d++) {
            float4 kvv = *(const float4*)&kvs[d][e];
            a0 += q[d] * kvv.x; a1 += q[d] * kvv.y;
            a2 += q[d] * kvv.z; a3 += q[d] * kvv.w;
        }
        *(float4*)(yrow + e) = make_float4(a0 * inv, a1 * inv, a2 * inv, a3 * inv);
    }
}

// ---------------------------------------------------------------------------
extern "C" void kernel_launch(void* const* d_in, const int* in_sizes, int n_in,
                              void* d_out, int out_size)
{
    const float* x      = (const float*)d_in[0];   // (4, 4096, 1024)
    const float* w_qkv  = (const float*)d_in[1];   // (1024, 3072)
    const float* w_proj = (const float*)d_in[2];   // (1024, 1024)
    const float* b_proj = (const float*)d_in[3];   // (1024,)
    float* out = (float*)d_out;

    float *qkv_p, *y_p;
    cudaGetSymbolAddress((void**)&qkv_p, g_qkv);
    cudaGetSymbolAddress((void**)&y_p,   g_y);

    // 1) qkv = x @ w_qkv, with elu+1 fused on q,k columns
    {
        dim3 grid(QKVC / 128, ROWS / 128);
        sgemm_kernel<1><<<grid, 256>>>(x, w_qkv, nullptr, qkv_p, ROWS, QKVC, CH);
    }
    // 2) kv outer-product accumulation + sum_k
    kv_kernel<<<BH, 256>>>();
    // 3) numerator / denominator -> merged-head y
    {
        dim3 grid(SEQ / 128, BH);
        y_kernel<<<grid, 128>>>();
    }
    // 4) out = y @ w_proj + b_proj
    {
        dim3 grid(CH / 128, ROWS / 128);
        sgemm_kernel<2><<<grid, 256>>>(y_p, w_proj, b_proj, out, ROWS, CH, CH);
    }
}

// round 3
// speedup vs baseline: 2.4203x; 2.4203x over previous
#include <cuda_runtime.h>
#include <cuda_bf16.h>
#include <math.h>
#include <stdint.h>

// Problem constants: B=4, N=4096, C=1024, H=16, D=64
#define BATCH 4
#define SEQ   4096
#define CH    1024
#define HEADS 16
#define HD    64
#define ROWS  (BATCH*SEQ)        // 16384
#define QKVC  (3*CH)             // 3072
#define BH    (BATCH*HEADS)      // 64

// ---------------- scratch (device globals: allocation-free) ----------------
__device__ float g_qkv [(size_t)ROWS * QKVC];   // qkv projection (elu+1 on q,k)
__device__ float g_kv  [(size_t)BH * HD * HD];  // per-head kv = k^T v
__device__ float g_sumk[(size_t)BH * HD];       // sum over n of k
__device__ float g_y   [(size_t)ROWS * CH];     // merged-head attention output

// fp32 -> tf32 with round-to-nearest (cuts quantization error ~2x vs truncation)
__device__ __forceinline__ float f2tf32(float x) {
    uint32_t r;
    asm("cvt.rna.tf32.f32 %0, %1;" : "=r"(r) : "f"(x));
    return __uint_as_float(r);
}

// ---------------- TF32 tensor-core GEMM: C = A(MxK) @ B(KxN) ---------------
// 128x128 block tile, BK=16 (2 k8 steps), 256 threads = 8 warps (2x4),
// warp tile 64x32 = 4x4 m16n8k8 fragments. Double-buffered smem.
// MODE 1: elu+1 on columns < 2048 (q,k). MODE 2: +bias.
template <int MODE>
__global__ __launch_bounds__(256)
void mma_gemm(const float* __restrict__ A, const float* __restrict__ B,
              const float* __restrict__ bias, float* __restrict__ C,
              int M, int N, int K)
{
    const int BK = 16;
    const int LDA = 20;    // As row stride
    const int LDB = 136;   // Bs row stride

    __shared__ float As[2][128 * LDA];
    __shared__ float Bs[2][BK * LDB];

    const int tid   = threadIdx.x;
    const int lane  = tid & 31;
    const int warp  = tid >> 5;
    const int warpM = warp >> 2;   // 0..1
    const int warpN = warp & 3;    // 0..3
    const int g     = lane >> 2;   // groupID 0..7
    const int tig   = lane & 3;    // thread-in-group

    // global load indices
    const int aRow  = tid >> 2;    // 0..63 (+64)
    const int aCol4 = tid & 3;
    const int bRow  = tid >> 5;    // 0..7 (+8)
    const int bCol4 = tid & 31;

    const float* Aptr = A + (size_t)blockIdx.y * 128 * K;
    const float* Bptr = B + (size_t)blockIdx.x * 128;

    float acc[4][4][4];
    #pragma unroll
    for (int i = 0; i < 4; i++)
        #pragma unroll
        for (int j = 0; j < 4; j++)
            #pragma unroll
            for (int l = 0; l < 4; l++) acc[i][j][l] = 0.f;

    float4 aReg[2], bReg[2];

    auto ldg = [&](int k0) {
        #pragma unroll
        for (int i = 0; i < 2; i++)
            aReg[i] = *(const float4*)(Aptr + (size_t)(aRow + i * 64) * K + k0 + aCol4 * 4);
        #pragma unroll
        for (int i = 0; i < 2; i++)
            bReg[i] = *(const float4*)(Bptr + (size_t)(k0 + bRow + i * 8) * N + bCol4 * 4);
    };
    auto sts = [&](int buf) {
        #pragma unroll
        for (int i = 0; i < 2; i++) {
            int r = aRow + i * 64;
            float* p = &As[buf][r * LDA + aCol4 * 4];
            p[0] = f2tf32(aReg[i].x); p[1] = f2tf32(aReg[i].y);
            p[2] = f2tf32(aReg[i].z); p[3] = f2tf32(aReg[i].w);
        }
        #pragma unroll
        for (int i = 0; i < 2; i++) {
            int r = bRow + i * 8;
            float* p = &Bs[buf][r * LDB + bCol4 * 4];
            p[0] = f2tf32(bReg[i].x); p[1] = f2tf32(bReg[i].y);
            p[2] = f2tf32(bReg[i].z); p[3] = f2tf32(bReg[i].w);
        }
    };

    auto compute = [&](int buf) {
        #pragma unroll
        for (int ks = 0; ks < 2; ks++) {
            const int k0 = ks * 8;
            uint32_t af[4][4], bf[4][2];
            #pragma unroll
            for (int mi = 0; mi < 4; mi++) {
                int base = (warpM * 64 + mi * 16 + g) * LDA + k0 + tig;
                af[mi][0] = __float_as_uint(As[buf][base]);
                af[mi][1] = __float_as_uint(As[buf][base + 8 * LDA]);
                af[mi][2] = __float_as_uint(As[buf][base + 4]);
                af[mi][3] = __float_as_uint(As[buf][base + 8 * LDA + 4]);
            }
            #pragma unroll
            for (int ni = 0; ni < 4; ni++) {
                int c = warpN * 32 + ni * 8 + g;
                // FIX R3: B fragment rows must include the k-step offset k0
                bf[ni][0] = __float_as_uint(Bs[buf][(k0 + tig) * LDB + c]);
                bf[ni][1] = __float_as_uint(Bs[buf][(k0 + tig + 4) * LDB + c]);
            }
            #pragma unroll
            for (int mi = 0; mi < 4; mi++)
                #pragma unroll
                for (int ni = 0; ni < 4; ni++) {
                    asm volatile(
                        "mma.sync.aligned.m16n8k8.row.col.f32.tf32.tf32.f32 "
                        "{%0,%1,%2,%3}, {%4,%5,%6,%7}, {%8,%9}, {%0,%1,%2,%3};\n"
                        : "+f"(acc[mi][ni][0]), "+f"(acc[mi][ni][1]),
                          "+f"(acc[mi][ni][2]), "+f"(acc[mi][ni][3])
                        : "r"(af[mi][0]), "r"(af[mi][1]), "r"(af[mi][2]), "r"(af[mi][3]),
                          "r"(bf[ni][0]), "r"(bf[ni][1]));
                }
        }
    };

    // prologue
    ldg(0);
    sts(0);
    __syncthreads();

    const int nTiles = K / BK;
    for (int t = 0; t < nTiles; t++) {
        const int cur = t & 1;
        if (t + 1 < nTiles) ldg((t + 1) * BK);
        compute(cur);
        if (t + 1 < nTiles) {
            sts(cur ^ 1);
            __syncthreads();
        }
    }

    // epilogue
    #pragma unroll
    for (int mi = 0; mi < 4; mi++) {
        #pragma unroll
        for (int ni = 0; ni < 4; ni++) {
            const int r0 = blockIdx.y * 128 + warpM * 64 + mi * 16 + g;
            const int c0 = blockIdx.x * 128 + warpN * 32 + ni * 8 + 2 * tig;
            #pragma unroll
            for (int half = 0; half < 2; half++) {
                float v0 = acc[mi][ni][half * 2 + 0];
                float v1 = acc[mi][ni][half * 2 + 1];
                if (MODE == 1) {
                    if (c0 < 2 * CH)     v0 = (v0 > 0.f) ? (v0 + 1.f) : expf(v0);
                    if (c0 + 1 < 2 * CH) v1 = (v1 > 0.f) ? (v1 + 1.f) : expf(v1);
                } else if (MODE == 2) {
                    v0 += bias[c0]; v1 += bias[c0 + 1];
                }
                *(float2*)(C + (size_t)(r0 + half * 8) * N + c0) = make_float2(v0, v1);
            }
        }
    }
}

// ---------------- kv = sum_n k[n,d]*v[n,e] and sumk[d] ---------------------
__global__ __launch_bounds__(256)
void kv_kernel()
{
    const int bh = blockIdx.x;
    const int b  = bh / HEADS;
    const int h  = bh % HEADS;

    __shared__ float ks[32][HD];
    __shared__ float vs[32][HD];

    const int tid = threadIdx.x;
    const int e0  = (tid % 16) * 4;
    const int d0  = (tid / 16) * 4;

    float acc[4][4] = {};
    float sacc[4]   = {0.f, 0.f, 0.f, 0.f};

    const float* base = g_qkv + (size_t)b * SEQ * QKVC + h * HD;

    for (int n0 = 0; n0 < SEQ; n0 += 32) {
        #pragma unroll
        for (int i = 0; i < 2; i++) {
            int idx = tid + i * 256;
            int r   = idx / 16;
            int c4  = idx % 16;
            const float* rowp = base + (size_t)(n0 + r) * QKVC;
            *(float4*)&ks[r][c4 * 4] = *(const float4*)(rowp + CH     + c4 * 4);
            *(float4*)&vs[r][c4 * 4] = *(const float4*)(rowp + 2 * CH + c4 * 4);
        }
        __syncthreads();

        #pragma unroll 4
        for (int nn = 0; nn < 32; nn++) {
            float kr[4], vr[4];
            #pragma unroll
            for (int i = 0; i < 4; i++) kr[i] = ks[nn][d0 + i];
            #pragma unroll
            for (int j = 0; j < 4; j++) vr[j] = vs[nn][e0 + j];
            #pragma unroll
            for (int i = 0; i < 4; i++)
                #pragma unroll
                for (int j = 0; j < 4; j++)
                    acc[i][j] += kr[i] * vr[j];
            if (e0 == 0) {
                #pragma unroll
                for (int i = 0; i < 4; i++) sacc[i] += kr[i];
            }
        }
        __syncthreads();
    }

    float* kvp = g_kv + (size_t)bh * HD * HD;
    #pragma unroll
    for (int i = 0; i < 4; i++)
        *(float4*)&kvp[(d0 + i) * HD + e0] =
            make_float4(acc[i][0], acc[i][1], acc[i][2], acc[i][3]);
    if (e0 == 0) {
        #pragma unroll
        for (int i = 0; i < 4; i++) g_sumk[bh * HD + d0 + i] = sacc[i];
    }
}

// ---------------- y[n,e] = (q[n,:]·kv[:,e]) / (q[n,:]·sumk) ----------------
__global__ __launch_bounds__(128)
void y_kernel()
{
    const int bh  = blockIdx.y;
    const int b   = bh / HEADS;
    const int h   = bh % HEADS;
    const int tid = threadIdx.x;
    const int n   = blockIdx.x * 128 + tid;

    __shared__ float kvs[HD][HD];
    __shared__ float sks[HD];

    const float* kvp = g_kv + (size_t)bh * HD * HD;
    for (int i = tid; i < HD * HD / 4; i += 128)
        ((float4*)kvs)[i] = ((const float4*)kvp)[i];
    if (tid < HD) sks[tid] = g_sumk[bh * HD + tid];
    __syncthreads();

    const float* qrow = g_qkv + ((size_t)b * SEQ + n) * QKVC + h * HD;
    float q[HD];
    #pragma unroll
    for (int d = 0; d < HD; d += 4) {
        float4 t = *(const float4*)(qrow + d);
        q[d] = t.x; q[d + 1] = t.y; q[d + 2] = t.z; q[d + 3] = t.w;
    }

    float denom = 0.f;
    #pragma unroll
    for (int d = 0; d < HD; d++) denom += q[d] * sks[d];
    const float inv = 1.0f / denom;

    float* yrow = g_y + ((size_t)b * SEQ + n) * CH + h * HD;
    #pragma unroll 4
    for (int e = 0; e < HD; e += 4) {
        float a0 = 0.f, a1 = 0.f, a2 = 0.f, a3 = 0.f;
        #pragma unroll
        for (int d = 0; d < HD; d++) {
            float4 kvv = *(const float4*)&kvs[d][e];
            a0 += q[d] * kvv.x; a1 += q[d] * kvv.y;
            a2 += q[d] * kvv.z; a3 += q[d] * kvv.w;
        }
        *(float4*)(yrow + e) = make_float4(a0 * inv, a1 * inv, a2 * inv, a3 * inv);
    }
}

// ---------------------------------------------------------------------------
extern "C" void kernel_launch(void* const* d_in, const int* in_sizes, int n_in,
                              void* d_out, int out_size)
{
    const float* x      = (const float*)d_in[0];   // (4, 4096, 1024)
    const float* w_qkv  = (const float*)d_in[1];   // (1024, 3072)
    const float* w_proj = (const float*)d_in[2];   // (1024, 1024)
    const float* b_proj = (const float*)d_in[3];   // (1024,)
    float* out = (float*)d_out;

    float *qkv_p, *y_p;
    cudaGetSymbolAddress((void**)&qkv_p, g_qkv);
    cudaGetSymbolAddress((void**)&y_p,   g_y);

    // 1) qkv = x @ w_qkv (tf32 tensor cores), elu+1 fused on q,k columns
    {
        dim3 grid(QKVC / 128, ROWS / 128);
        mma_gemm<1><<<grid, 256>>>(x, w_qkv, nullptr, qkv_p, ROWS, QKVC, CH);
    }
    // 2) kv outer-product accumulation + sum_k
    kv_kernel<<<BH, 256>>>();
    // 3) numerator / denominator -> merged-head y
    {
        dim3 grid(SEQ / 128, BH);
        y_kernel<<<grid, 128>>>();
    }
    // 4) out = y @ w_proj + b_proj (tf32 tensor cores)
    {
        dim3 grid(CH / 128, ROWS / 128);
        mma_gemm<2><<<grid, 256>>>(y_p, w_proj, b_proj, out, ROWS, CH, CH);
    }
}

// round 4
// speedup vs baseline: 2.5569x; 1.0564x over previous
#include <cuda_runtime.h>
#include <cuda_bf16.h>
#include <math.h>
#include <stdint.h>

// Problem constants: B=4, N=4096, C=1024, H=16, D=64
#define BATCH 4
#define SEQ   4096
#define CH    1024
#define HEADS 16
#define HD    64
#define ROWS  (BATCH*SEQ)        // 16384
#define QKVC  (3*CH)             // 3072
#define BH    (BATCH*HEADS)      // 64
#define KVCHUNKS 8

// ---------------- scratch (device globals: allocation-free) ----------------
__device__ float g_qkv  [(size_t)ROWS * QKVC];
__device__ float g_kv   [(size_t)BH * HD * HD];
__device__ float g_sumk [(size_t)BH * HD];
__device__ float g_y    [(size_t)ROWS * CH];
__device__ float g_kvp  [(size_t)KVCHUNKS * BH * HD * HD];
__device__ float g_sumkp[(size_t)KVCHUNKS * BH * HD];

// fp32 -> tf32 round-to-nearest
__device__ __forceinline__ float f2tf32(float x) {
    uint32_t r;
    asm("cvt.rna.tf32.f32 %0, %1;" : "=r"(r) : "f"(x));
    return __uint_as_float(r);
}

// ---------------- TF32 tensor-core GEMM: C = A(MxK) @ B(KxN) ---------------
// Block tile 128x256, BK=16, 256 threads = 8 warps (2x4), warp tile 64x64
// (4x8 m16n8k8 fragments). Double-buffered, swizzled smem (48KB exactly).
// MODE 1: elu+1 on columns < 2048. MODE 2: +bias.
template <int MODE>
__global__ __launch_bounds__(256)
void mma_gemm(const float* __restrict__ A, const float* __restrict__ B,
              const float* __restrict__ bias, float* __restrict__ C,
              int M, int N, int K)
{
    const int BK = 16;

    __shared__ float As[2][128 * 16];   // 16 KB
    __shared__ float Bs[2][16 * 256];   // 32 KB

    const int tid   = threadIdx.x;
    const int lane  = tid & 31;
    const int warp  = tid >> 5;
    const int warpM = warp >> 2;   // 0..1
    const int warpN = warp & 3;    // 0..3
    const int g     = lane >> 2;   // 0..7
    const int tig   = lane & 3;    // 0..3

    const float* Aptr = A + (size_t)blockIdx.y * 128 * K;
    const float* Bptr = B + (size_t)blockIdx.x * 256;

    // A swizzle: element (r,k) at float r*16 + perm, perm = 4*(((k>>2)+((r>>1)&3))&3) + (k&3)
    // B swizzle: element (k,c) at float k*256 + ((c + 8*k)&255)
    float acc[4][8][4];
    #pragma unroll
    for (int i = 0; i < 4; i++)
        #pragma unroll
        for (int j = 0; j < 8; j++)
            #pragma unroll
            for (int l = 0; l < 4; l++) acc[i][j][l] = 0.f;

    float4 aReg[2], bReg[4];

    const int aRow0 = tid >> 2;          // +0 via idx; two iters cover 512 float4
    const int bCol4 = tid & 63;          // B: 64 float4 per row
    const int bRow0 = tid >> 6;          // 0..3 (+4,+8,+12)

    auto ldg = [&](int k0) {
        #pragma unroll
        for (int it = 0; it < 2; it++) {
            int idx = tid + it * 256;
            int r = idx >> 2, c4 = idx & 3;
            aReg[it] = *(const float4*)(Aptr + (size_t)r * K + k0 + c4 * 4);
        }
        #pragma unroll
        for (int it = 0; it < 4; it++) {
            int r = bRow0 + it * 4;
            bReg[it] = *(const float4*)(Bptr + (size_t)(k0 + r) * N + bCol4 * 4);
        }
    };
    auto sts = [&](int buf) {
        #pragma unroll
        for (int it = 0; it < 2; it++) {
            int idx = tid + it * 256;
            int r = idx >> 2, c4 = idx & 3;
            int sc4 = (c4 + ((r >> 1) & 3)) & 3;
            float4 t;
            t.x = f2tf32(aReg[it].x); t.y = f2tf32(aReg[it].y);
            t.z = f2tf32(aReg[it].z); t.w = f2tf32(aReg[it].w);
            *(float4*)&As[buf][r * 16 + sc4 * 4] = t;
        }
        #pragma unroll
        for (int it = 0; it < 4; it++) {
            int r = bRow0 + it * 4;
            int sc = (bCol4 * 4 + 8 * r) & 255;
            float4 t;
            t.x = f2tf32(bReg[it].x); t.y = f2tf32(bReg[it].y);
            t.z = f2tf32(bReg[it].z); t.w = f2tf32(bReg[it].w);
            *(float4*)&Bs[buf][r * 256 + sc] = t;
        }
    };

    auto aoff = [&](int r, int k) -> int {
        return r * 16 + ((((k >> 2) + ((r >> 1) & 3)) & 3) * 4) + (k & 3);
    };
    auto boff = [&](int k, int c) -> int {
        return k * 256 + ((c + 8 * k) & 255);
    };

    auto compute = [&](int buf) {
        #pragma unroll
        for (int ks = 0; ks < 2; ks++) {
            const int k0 = ks * 8;
            uint32_t af[4][4], bf[8][2];
            #pragma unroll
            for (int mi = 0; mi < 4; mi++) {
                int r = warpM * 64 + mi * 16 + g;
                af[mi][0] = __float_as_uint(As[buf][aoff(r,     k0 + tig)]);
                af[mi][1] = __float_as_uint(As[buf][aoff(r + 8, k0 + tig)]);
                af[mi][2] = __float_as_uint(As[buf][aoff(r,     k0 + tig + 4)]);
                af[mi][3] = __float_as_uint(As[buf][aoff(r + 8, k0 + tig + 4)]);
            }
            #pragma unroll
            for (int ni = 0; ni < 8; ni++) {
                int c = warpN * 64 + ni * 8 + g;
                bf[ni][0] = __float_as_uint(Bs[buf][boff(k0 + tig,     c)]);
                bf[ni][1] = __float_as_uint(Bs[buf][boff(k0 + tig + 4, c)]);
            }
            #pragma unroll
            for (int mi = 0; mi < 4; mi++)
                #pragma unroll
                for (int ni = 0; ni < 8; ni++) {
                    asm volatile(
                        "mma.sync.aligned.m16n8k8.row.col.f32.tf32.tf32.f32 "
                        "{%0,%1,%2,%3}, {%4,%5,%6,%7}, {%8,%9}, {%0,%1,%2,%3};\n"
                        : "+f"(acc[mi][ni][0]), "+f"(acc[mi][ni][1]),
                          "+f"(acc[mi][ni][2]), "+f"(acc[mi][ni][3])
                        : "r"(af[mi][0]), "r"(af[mi][1]), "r"(af[mi][2]), "r"(af[mi][3]),
                          "r"(bf[ni][0]), "r"(bf[ni][1]));
                }
        }
    };

    ldg(0);
    sts(0);
    __syncthreads();

    const int nTiles = K / BK;
    for (int t = 0; t < nTiles; t++) {
        const int cur = t & 1;
        if (t + 1 < nTiles) ldg((t + 1) * BK);
        compute(cur);
        if (t + 1 < nTiles) {
            sts(cur ^ 1);
            __syncthreads();
        }
    }

    // epilogue
    #pragma unroll
    for (int mi = 0; mi < 4; mi++) {
        #pragma unroll
        for (int ni = 0; ni < 8; ni++) {
            const int r0 = blockIdx.y * 128 + warpM * 64 + mi * 16 + g;
            const int c0 = blockIdx.x * 256 + warpN * 64 + ni * 8 + 2 * tig;
            #pragma unroll
            for (int half = 0; half < 2; half++) {
                float v0 = acc[mi][ni][half * 2 + 0];
                float v1 = acc[mi][ni][half * 2 + 1];
                if (MODE == 1) {
                    if (c0 < 2 * CH)     v0 = (v0 > 0.f) ? (v0 + 1.f) : expf(v0);
                    if (c0 + 1 < 2 * CH) v1 = (v1 > 0.f) ? (v1 + 1.f) : expf(v1);
                } else if (MODE == 2) {
                    v0 += bias[c0]; v1 += bias[c0 + 1];
                }
                *(float2*)(C + (size_t)(r0 + half * 8) * N + c0) = make_float2(v0, v1);
            }
        }
    }
}

// ---------------- kv partial: chunks of SEQ in parallel --------------------
__global__ __launch_bounds__(256)
void kv_partial_kernel()
{
    const int bh    = blockIdx.x;          // 0..63
    const int chunk = blockIdx.y;          // 0..7
    const int b  = bh / HEADS;
    const int h  = bh % HEADS;

    __shared__ float ks[32][HD];
    __shared__ float vs[32][HD];

    const int tid = threadIdx.x;
    const int e0  = (tid % 16) * 4;
    const int d0  = (tid / 16) * 4;

    float acc[4][4] = {};
    float sacc[4]   = {0.f, 0.f, 0.f, 0.f};

    const float* base = g_qkv + (size_t)b * SEQ * QKVC + h * HD;
    const int nBeg = chunk * (SEQ / KVCHUNKS);
    const int nEnd = nBeg + (SEQ / KVCHUNKS);

    for (int n0 = nBeg; n0 < nEnd; n0 += 32) {
        #pragma unroll
        for (int i = 0; i < 2; i++) {
            int idx = tid + i * 256;
            int r   = idx / 16;
            int c4  = idx % 16;
            const float* rowp = base + (size_t)(n0 + r) * QKVC;
            *(float4*)&ks[r][c4 * 4] = *(const float4*)(rowp + CH     + c4 * 4);
            *(float4*)&vs[r][c4 * 4] = *(const float4*)(rowp + 2 * CH + c4 * 4);
        }
        __syncthreads();

        #pragma unroll 4
        for (int nn = 0; nn < 32; nn++) {
            float kr[4], vr[4];
            #pragma unroll
            for (int i = 0; i < 4; i++) kr[i] = ks[nn][d0 + i];
            #pragma unroll
            for (int j = 0; j < 4; j++) vr[j] = vs[nn][e0 + j];
            #pragma unroll
            for (int i = 0; i < 4; i++)
                #pragma unroll
                for (int j = 0; j < 4; j++)
                    acc[i][j] += kr[i] * vr[j];
            if (e0 == 0) {
                #pragma unroll
                for (int i = 0; i < 4; i++) sacc[i] += kr[i];
            }
        }
        __syncthreads();
    }

    float* kvp = g_kvp + ((size_t)chunk * BH + bh) * HD * HD;
    #pragma unroll
    for (int i = 0; i < 4; i++)
        *(float4*)&kvp[(d0 + i) * HD + e0] =
            make_float4(acc[i][0], acc[i][1], acc[i][2], acc[i][3]);
    if (e0 == 0) {
        #pragma unroll
        for (int i = 0; i < 4; i++)
            g_sumkp[((size_t)chunk * BH + bh) * HD + d0 + i] = sacc[i];
    }
}

__global__ __launch_bounds__(256)
void kv_reduce_kernel()
{
    const int bh  = blockIdx.x;
    const int tid = threadIdx.x;
    // kv: 4096 elements, 256 threads -> 16 each
    for (int i = tid; i < HD * HD; i += 256) {
        float s = 0.f;
        #pragma unroll
        for (int c = 0; c < KVCHUNKS; c++)
            s += g_kvp[((size_t)c * BH + bh) * HD * HD + i];
        g_kv[(size_t)bh * HD * HD + i] = s;
    }
    if (tid < HD) {
        float s = 0.f;
        #pragma unroll
        for (int c = 0; c < KVCHUNKS; c++)
            s += g_sumkp[((size_t)c * BH + bh) * HD + tid];
        g_sumk[(size_t)bh * HD + tid] = s;
    }
}

// ---------------- y[n,e] = (q[n,:]·kv[:,e]) / (q[n,:]·sumk) ----------------
__global__ __launch_bounds__(128)
void y_kernel()
{
    const int bh  = blockIdx.y;
    const int b   = bh / HEADS;
    const int h   = bh % HEADS;
    const int tid = threadIdx.x;
    const int n   = blockIdx.x * 128 + tid;

    __shared__ float kvs[HD][HD];
    __shared__ float sks[HD];

    const float* kvp = g_kv + (size_t)bh * HD * HD;
    for (int i = tid; i < HD * HD / 4; i += 128)
        ((float4*)kvs)[i] = ((const float4*)kvp)[i];
    if (tid < HD) sks[tid] = g_sumk[bh * HD + tid];
    __syncthreads();

    const float* qrow = g_qkv + ((size_t)b * SEQ + n) * QKVC + h * HD;
    float q[HD];
    #pragma unroll
    for (int d = 0; d < HD; d += 4) {
        float4 t = *(const float4*)(qrow + d);
        q[d] = t.x; q[d + 1] = t.y; q[d + 2] = t.z; q[d + 3] = t.w;
    }

    float denom = 0.f;
    #pragma unroll
    for (int d = 0; d < HD; d++) denom += q[d] * sks[d];
    const float inv = 1.0f / denom;

    float* yrow = g_y + ((size_t)b * SEQ + n) * CH + h * HD;
    #pragma unroll 4
    for (int e = 0; e < HD; e += 4) {
        float a0 = 0.f, a1 = 0.f, a2 = 0.f, a3 = 0.f;
        #pragma unroll
        for (int d = 0; d < HD; d++) {
            float4 kvv = *(const float4*)&kvs[d][e];
            a0 += q[d] * kvv.x; a1 += q[d] * kvv.y;
            a2 += q[d] * kvv.z; a3 += q[d] * kvv.w;
        }
        *(float4*)(yrow + e) = make_float4(a0 * inv, a1 * inv, a2 * inv, a3 * inv);
    }
}

// ---------------------------------------------------------------------------
extern "C" void kernel_launch(void* const* d_in, const int* in_sizes, int n_in,
                              void* d_out, int out_size)
{
    const float* x      = (const float*)d_in[0];
    const float* w_qkv  = (const float*)d_in[1];
    const float* w_proj = (const float*)d_in[2];
    const float* b_proj = (const float*)d_in[3];
    float* out = (float*)d_out;

    float *qkv_p, *y_p;
    cudaGetSymbolAddress((void**)&qkv_p, g_qkv);
    cudaGetSymbolAddress((void**)&y_p,   g_y);

    // 1) qkv = x @ w_qkv (tf32), elu+1 fused on q,k
    {
        dim3 grid(QKVC / 256, ROWS / 128);
        mma_gemm<1><<<grid, 256>>>(x, w_qkv, nullptr, qkv_p, ROWS, QKVC, CH);
    }
    // 2) kv outer product (split over seq chunks) + reduce
    {
        dim3 grid(BH, KVCHUNKS);
        kv_partial_kernel<<<grid, 256>>>();
        kv_reduce_kernel<<<BH, 256>>>();
    }
    // 3) numerator / denominator -> y
    {
        dim3 grid(SEQ / 128, BH);
        y_kernel<<<grid, 128>>>();
    }
    // 4) out = y @ w_proj + b_proj (tf32)
    {
        dim3 grid(CH / 256, ROWS / 128);
        mma_gemm<2><<<grid, 256>>>(y_p, w_proj, b_proj, out, ROWS, CH, CH);
    }
}

// round 6
// speedup vs baseline: 4.8352x; 1.8911x over previous
#include <cuda_runtime.h>
#include <cuda_fp16.h>
#include <math.h>
#include <stdint.h>

// Problem constants: B=4, N=4096, C=1024, H=16, D=64
#define BATCH 4
#define SEQ   4096
#define CH    1024
#define HEADS 16
#define HD    64
#define ROWS  (BATCH*SEQ)        // 16384
#define QKVC  (3*CH)             // 3072
#define BH    (BATCH*HEADS)      // 64
#define KVCHUNKS 8

// ---------------- scratch (device globals: allocation-free) ----------------
__device__ float g_qkv [(size_t)ROWS * QKVC];          // GEMM1 out fp32 (elu+1 on q,k)
__device__ __align__(256) __half g_xh    [(size_t)ROWS * CH];    // x in fp16
__device__ __align__(256) __half g_wqkvh [(size_t)CH * QKVC];    // w_qkv fp16 (same layout)
__device__ __align__(256) __half g_wprojh[(size_t)CH * CH];      // w_proj fp16
__device__ __align__(256) __half g_yh    [(size_t)ROWS * CH];    // attention out fp16
__device__ float g_kv   [(size_t)BH * HD * HD];
__device__ float g_sumk [(size_t)BH * HD];
__device__ float g_kvp  [(size_t)KVCHUNKS * BH * HD * HD];
__device__ float g_sumkp[(size_t)KVCHUNKS * BH * HD];

__device__ __forceinline__ uint32_t smem_u32(const void* p) {
    uint32_t a;
    asm("{ .reg .u64 t; cvta.to.shared.u64 t, %1; cvt.u32.u64 %0, t; }" : "=r"(a) : "l"(p));
    return a;
}

// ================= fp16 tensor-core GEMM: C = A(MxK) @ B(KxN) ==============
// Block 128x256, BK=32, 256 threads = 8 warps (2x4), warp tile 64x64,
// mma.m16n8k16 (4 mi x 8 ni x 2 ks). Double-buffered swizzled smem (48KB).
// A smem: 128B atoms = 2 rows of 32 halves; 16B chunk XOR-swizzled by atom row.
// B smem: rows of 256 halves (512B); 16B chunk XOR-swizzled by k&7.
// MODE 1: elu+1 on columns < 2048. MODE 2: +bias.
#define BKH 32
template <int MODE>
__global__ __launch_bounds__(256, 1)
void hgemm(const __half* __restrict__ A, const __half* __restrict__ B,
           const float* __restrict__ bias, float* __restrict__ C,
           int Ncols, int K)
{
    __shared__ __align__(16) __half smA[2][128 * BKH];   // 8KB / buf
    __shared__ __align__(16) __half smB[2][BKH * 256];   // 16KB / buf

    const int tid   = threadIdx.x;
    const int lane  = tid & 31;
    const int warp  = tid >> 5;
    const int warpM = warp >> 2;   // 0..1
    const int warpN = warp & 3;    // 0..3
    const int g     = lane >> 2;   // 0..7
    const int tig   = lane & 3;    // 0..3

    const __half* Aptr = A + (size_t)blockIdx.y * 128 * K;
    const __half* Bptr = B + (size_t)blockIdx.x * 256;

    float acc[4][8][4];
    #pragma unroll
    for (int i = 0; i < 4; i++)
        #pragma unroll
        for (int j = 0; j < 8; j++)
            #pragma unroll
            for (int l = 0; l < 4; l++) acc[i][j][l] = 0.f;

    uint4 stA[2], stB[4];

    auto ldg = [&](int k0) {
        #pragma unroll
        for (int it = 0; it < 2; it++) {
            int id = tid + it * 256;
            int r = id >> 2, kc = (id & 3) << 3;
            stA[it] = *(const uint4*)(Aptr + (size_t)r * K + k0 + kc);
        }
        #pragma unroll
        for (int it = 0; it < 4; it++) {
            int id = tid + it * 256;
            int kr = id >> 5, nc = (id & 31) << 3;
            stB[it] = *(const uint4*)(Bptr + (size_t)(k0 + kr) * Ncols + nc);
        }
    };
    auto sts = [&](int buf) {
        char* baseA = (char*)smA[buf];
        char* baseB = (char*)smB[buf];
        #pragma unroll
        for (int it = 0; it < 2; it++) {
            int id = tid + it * 256;
            int r = id >> 2, kc = (id & 3) << 3;
            int R = r >> 1;
            int off = ((r & 1) << 6) | (kc << 1);
            *(uint4*)(baseA + R * 128 + (off ^ ((R & 7) << 4))) = stA[it];
        }
        #pragma unroll
        for (int it = 0; it < 4; it++) {
            int id = tid + it * 256;
            int kr = id >> 5, nc = (id & 31) << 3;
            *(uint4*)(baseB + kr * 512 + (((nc << 1)) ^ ((kr & 7) << 4))) = stB[it];
        }
    };

    auto compute = [&](int buf) {
        const uint32_t a_base = smem_u32(smA[buf]);
        const uint32_t b_base = smem_u32(smB[buf]);
        #pragma unroll
        for (int ks = 0; ks < 2; ks++) {
            uint32_t af[4][4], bf[8][2];
            #pragma unroll
            for (int mi = 0; mi < 4; mi++) {
                // lanes 0-15: rows base..base+15 @ k = ks*16; lanes 16-31: same rows @ k+8
                int r = warpM * 64 + mi * 16 + (lane & 15);
                int k = ks * 16 + ((lane >> 4) << 3);
                int R = r >> 1;
                int off = ((r & 1) << 6) | (k << 1);
                uint32_t addr = a_base + R * 128 + (off ^ ((R & 7) << 4));
                asm volatile(
                    "ldmatrix.sync.aligned.m8n8.x4.shared.b16 {%0,%1,%2,%3}, [%4];"
                    : "=r"(af[mi][0]), "=r"(af[mi][1]), "=r"(af[mi][2]), "=r"(af[mi][3])
                    : "r"(addr));
            }
            #pragma unroll
            for (int nip = 0; nip < 4; nip++) {
                // lanes 0-15: k rows ks*16..+15 @ n0; lanes 16-31: same @ n0+8
                int k = ks * 16 + (lane & 15);
                int n = warpN * 64 + nip * 16 + ((lane >> 4) << 3);
                uint32_t addr = b_base + k * 512 + (((n << 1)) ^ ((k & 7) << 4));
                asm volatile(
                    "ldmatrix.sync.aligned.m8n8.x4.trans.shared.b16 {%0,%1,%2,%3}, [%4];"
                    : "=r"(bf[2 * nip][0]), "=r"(bf[2 * nip][1]),
                      "=r"(bf[2 * nip + 1][0]), "=r"(bf[2 * nip + 1][1])
                    : "r"(addr));
            }
            #pragma unroll
            for (int mi = 0; mi < 4; mi++)
                #pragma unroll
                for (int ni = 0; ni < 8; ni++) {
                    asm volatile(
                        "mma.sync.aligned.m16n8k16.row.col.f32.f16.f16.f32 "
                        "{%0,%1,%2,%3}, {%4,%5,%6,%7}, {%8,%9}, {%0,%1,%2,%3};\n"
                        : "+f"(acc[mi][ni][0]), "+f"(acc[mi][ni][1]),
                          "+f"(acc[mi][ni][2]), "+f"(acc[mi][ni][3])
                        : "r"(af[mi][0]), "r"(af[mi][1]), "r"(af[mi][2]), "r"(af[mi][3]),
                          "r"(bf[ni][0]), "r"(bf[ni][1]));
                }
        }
    };

    ldg(0);
    sts(0);
    __syncthreads();

    const int nTiles = K / BKH;
    for (int t = 0; t < nTiles; t++) {
        const int cur = t & 1;
        if (t + 1 < nTiles) ldg((t + 1) * BKH);
        compute(cur);
        if (t + 1 < nTiles) {
            sts(cur ^ 1);
            __syncthreads();
        }
    }

    // epilogue (fp32)
    #pragma unroll
    for (int mi = 0; mi < 4; mi++) {
        #pragma unroll
        for (int ni = 0; ni < 8; ni++) {
            const int r0 = blockIdx.y * 128 + warpM * 64 + mi * 16 + g;
            const int c0 = blockIdx.x * 256 + warpN * 64 + ni * 8 + 2 * tig;
            #pragma unroll
            for (int half_i = 0; half_i < 2; half_i++) {
                float v0 = acc[mi][ni][half_i * 2 + 0];
                float v1 = acc[mi][ni][half_i * 2 + 1];
                if (MODE == 1) {
                    if (c0 < 2 * CH)     v0 = (v0 > 0.f) ? (v0 + 1.f) : expf(v0);
                    if (c0 + 1 < 2 * CH) v1 = (v1 > 0.f) ? (v1 + 1.f) : expf(v1);
                } else if (MODE == 2) {
                    v0 += bias[c0]; v1 += bias[c0 + 1];
                }
                *(float2*)(C + (size_t)(r0 + half_i * 8) * Ncols + c0) = make_float2(v0, v1);
            }
        }
    }
}

// ================= prep: fp32 -> fp16 (rn) =================================
__global__ __launch_bounds__(256)
void cvt_f16_kernel(const float4* __restrict__ in, uint4* __restrict__ outp, int n8)
{
    int i = blockIdx.x * 256 + threadIdx.x;
    if (i < n8) {
        float4 a = in[2 * i], b = in[2 * i + 1];
        __half2 h0 = __floats2half2_rn(a.x, a.y);
        __half2 h1 = __floats2half2_rn(a.z, a.w);
        __half2 h2 = __floats2half2_rn(b.x, b.y);
        __half2 h3 = __floats2half2_rn(b.z, b.w);
        uint4 o;
        o.x = *reinterpret_cast<uint32_t*>(&h0);
        o.y = *reinterpret_cast<uint32_t*>(&h1);
        o.z = *reinterpret_cast<uint32_t*>(&h2);
        o.w = *reinterpret_cast<uint32_t*>(&h3);
        outp[i] = o;
    }
}

// ================= kv partial + reduce (fp32, unchanged math) ==============
__global__ __launch_bounds__(256)
void kv_partial_kernel()
{
    const int bh    = blockIdx.x;
    const int chunk = blockIdx.y;
    const int b = bh / HEADS, h = bh % HEADS;

    __shared__ float ks[32][HD];
    __shared__ float vs[32][HD];

    const int tid = threadIdx.x;
    const int e0 = (tid % 16) * 4;
    const int d0 = (tid / 16) * 4;

    float acc[4][4] = {};
    float sacc[4] = {0.f, 0.f, 0.f, 0.f};

    const float* base = g_qkv + (size_t)b * SEQ * QKVC + h * HD;
    const int nBeg = chunk * (SEQ / KVCHUNKS);
    const int nEnd = nBeg + (SEQ / KVCHUNKS);

    for (int n0 = nBeg; n0 < nEnd; n0 += 32) {
        #pragma unroll
        for (int i = 0; i < 2; i++) {
            int idx = tid + i * 256;
            int r = idx / 16, c4 = idx % 16;
            const float* rowp = base + (size_t)(n0 + r) * QKVC;
            *(float4*)&ks[r][c4 * 4] = *(const float4*)(rowp + CH     + c4 * 4);
            *(float4*)&vs[r][c4 * 4] = *(const float4*)(rowp + 2 * CH + c4 * 4);
        }
        __syncthreads();
        #pragma unroll 4
        for (int nn = 0; nn < 32; nn++) {
            float kr[4], vr[4];
            #pragma unroll
            for (int i = 0; i < 4; i++) kr[i] = ks[nn][d0 + i];
            #pragma unroll
            for (int j = 0; j < 4; j++) vr[j] = vs[nn][e0 + j];
            #pragma unroll
            for (int i = 0; i < 4; i++)
                #pragma unroll
                for (int j = 0; j < 4; j++)
                    acc[i][j] += kr[i] * vr[j];
            if (e0 == 0) {
                #pragma unroll
                for (int i = 0; i < 4; i++) sacc[i] += kr[i];
            }
        }
        __syncthreads();
    }

    float* kvp = g_kvp + ((size_t)chunk * BH + bh) * HD * HD;
    #pragma unroll
    for (int i = 0; i < 4; i++)
        *(float4*)&kvp[(d0 + i) * HD + e0] =
            make_float4(acc[i][0], acc[i][1], acc[i][2], acc[i][3]);
    if (e0 == 0) {
        #pragma unroll
        for (int i = 0; i < 4; i++)
            g_sumkp[((size_t)chunk * BH + bh) * HD + d0 + i] = sacc[i];
    }
}

__global__ __launch_bounds__(256)
void kv_reduce_kernel()
{
    const int bh = blockIdx.x;
    const int tid = threadIdx.x;
    for (int i = tid; i < HD * HD; i += 256) {
        float s = 0.f;
        #pragma unroll
        for (int c = 0; c < KVCHUNKS; c++)
            s += g_kvp[((size_t)c * BH + bh) * HD * HD + i];
        g_kv[(size_t)bh * HD * HD + i] = s;
    }
    if (tid < HD) {
        float s = 0.f;
        #pragma unroll
        for (int c = 0; c < KVCHUNKS; c++)
            s += g_sumkp[((size_t)c * BH + bh) * HD + tid];
        g_sumk[(size_t)bh * HD + tid] = s;
    }
}

// ================= y = (q . kv) / (q . sumk), emitted as fp16 ==============
__global__ __launch_bounds__(128)
void y_kernel()
{
    const int bh = blockIdx.y;
    const int b = bh / HEADS, h = bh % HEADS;
    const int tid = threadIdx.x;
    const int n = blockIdx.x * 128 + tid;

    __shared__ float kvs[HD][HD];
    __shared__ float sks[HD];

    const float* kvp = g_kv + (size_t)bh * HD * HD;
    for (int i = tid; i < HD * HD / 4; i += 128)
        ((float4*)kvs)[i] = ((const float4*)kvp)[i];
    if (tid < HD) sks[tid] = g_sumk[bh * HD + tid];
    __syncthreads();

    const float* qrow = g_qkv + ((size_t)b * SEQ + n) * QKVC + h * HD;
    float q[HD];
    #pragma unroll
    for (int d = 0; d < HD; d += 4) {
        float4 t = *(const float4*)(qrow + d);
        q[d] = t.x; q[d + 1] = t.y; q[d + 2] = t.z; q[d + 3] = t.w;
    }

    float denom = 0.f;
    #pragma unroll
    for (int d = 0; d < HD; d++) denom += q[d] * sks[d];
    const float inv = 1.0f / denom;

    __half* yrow = g_yh + ((size_t)b * SEQ + n) * CH + h * HD;
    #pragma unroll 4
    for (int e = 0; e < HD; e += 4) {
        float a0 = 0.f, a1 = 0.f, a2 = 0.f, a3 = 0.f;
        #pragma unroll
        for (int d = 0; d < HD; d++) {
            float4 kvv = *(const float4*)&kvs[d][e];
            a0 += q[d] * kvv.x; a1 += q[d] * kvv.y;
            a2 += q[d] * kvv.z; a3 += q[d] * kvv.w;
        }
        __half2 p0 = __floats2half2_rn(a0 * inv, a1 * inv);
        __half2 p1 = __floats2half2_rn(a2 * inv, a3 * inv);
        uint2 o;
        o.x = *reinterpret_cast<uint32_t*>(&p0);
        o.y = *reinterpret_cast<uint32_t*>(&p1);
        *(uint2*)(yrow + e) = o;
    }
}

// ---------------------------------------------------------------------------
extern "C" void kernel_launch(void* const* d_in, const int* in_sizes, int n_in,
                              void* d_out, int out_size)
{
    const float* x      = (const float*)d_in[0];
    const float* w_qkv  = (const float*)d_in[1];
    const float* w_proj = (const float*)d_in[2];
    const float* b_proj = (const float*)d_in[3];
    float* out = (float*)d_out;

    float *qkv_p;
    __half *xh_p, *wqkvh_p, *wprojh_p, *yh_p;
    cudaGetSymbolAddress((void**)&qkv_p,    g_qkv);
    cudaGetSymbolAddress((void**)&xh_p,     g_xh);
    cudaGetSymbolAddress((void**)&wqkvh_p,  g_wqkvh);
    cudaGetSymbolAddress((void**)&wprojh_p, g_wprojh);
    cudaGetSymbolAddress((void**)&yh_p,     g_yh);

    // 0) convert inputs to fp16 (rn)
    cvt_f16_kernel<<<(ROWS * CH / 8 + 255) / 256, 256>>>(
        (const float4*)x, (uint4*)xh_p, ROWS * CH / 8);
    cvt_f16_kernel<<<(CH * QKVC / 8 + 255) / 256, 256>>>(
        (const float4*)w_qkv, (uint4*)wqkvh_p, CH * QKVC / 8);
    cvt_f16_kernel<<<(CH * CH / 8 + 255) / 256, 256>>>(
        (const float4*)w_proj, (uint4*)wprojh_p, CH * CH / 8);

    // 1) qkv = x @ w_qkv (fp16 tensor cores), elu+1 fused on q,k columns
    {
        dim3 grid(QKVC / 256, ROWS / 128);
        hgemm<1><<<grid, 256>>>(xh_p, wqkvh_p, nullptr, qkv_p, QKVC, CH);
    }
    // 2) kv outer product (seq-split) + reduce
    {
        dim3 grid(BH, KVCHUNKS);
        kv_partial_kernel<<<grid, 256>>>();
        kv_reduce_kernel<<<BH, 256>>>();
    }
    // 3) numerator / denominator -> y (fp16)
    {
        dim3 grid(SEQ / 128, BH);
        y_kernel<<<grid, 128>>>();
    }
    // 4) out = y @ w_proj + b_proj (fp16 tensor cores)
    {
        dim3 grid(CH / 256, ROWS / 128);
        hgemm<2><<<grid, 256>>>(yh_p, wprojh_p, b_proj, out, CH, CH);
    }
}

// round 7
// speedup vs baseline: 5.2936x; 1.0948x over previous
#include <cuda_runtime.h>
#include <cuda_fp16.h>
#include <math.h>
#include <stdint.h>

// Problem constants: B=4, N=4096, C=1024, H=16, D=64
#define BATCH 4
#define SEQ   4096
#define CH    1024
#define HEADS 16
#define HD    64
#define ROWS  (BATCH*SEQ)        // 16384
#define QKVC  (3*CH)             // 3072
#define BH    (BATCH*HEADS)      // 64
#define KVCHUNKS 8

// ---------------- scratch (device globals: allocation-free) ----------------
__device__ float g_qkv [(size_t)ROWS * QKVC];          // GEMM1 out fp32 (elu+1 on q,k)
__device__ __align__(256) __half g_xh    [(size_t)ROWS * CH];
__device__ __align__(256) __half g_wqkvh [(size_t)CH * QKVC];
__device__ __align__(256) __half g_wprojh[(size_t)CH * CH];
__device__ __align__(256) __half g_yh    [(size_t)ROWS * CH];
__device__ __align__(256) __half g_kvh   [(size_t)BH * HD * HD];   // kv fp16
__device__ float g_sumk [(size_t)BH * HD];
__device__ float g_kvp  [(size_t)KVCHUNKS * BH * HD * HD];
__device__ float g_sumkp[(size_t)KVCHUNKS * BH * HD];

__device__ __forceinline__ uint32_t smem_u32(const void* p) {
    uint32_t a;
    asm("{ .reg .u64 t; cvta.to.shared.u64 t, %1; cvt.u32.u64 %0, t; }" : "=r"(a) : "l"(p));
    return a;
}

// ================= fp16 GEMM with cp.async 4-stage pipeline ================
// Block 128x256, BK=32, 256 threads = 8 warps (2x4), warp tile 64x64,
// mma.m16n8k16. A smem: 128B atoms (2 rows x 32 halves), XOR swizzle.
// B smem: 512B rows, XOR swizzle by k&7. Dynamic smem: 4 stages x 24KB.
#define BKH 32
#define NST 4
#define STAGE_A (128 * BKH * 2)            // 8192 B
#define STAGE_B (BKH * 256 * 2)            // 16384 B
#define STAGE_SZ (STAGE_A + STAGE_B)       // 24576 B
#define HG_SMEM (NST * STAGE_SZ)           // 98304 B

template <int MODE>
__global__ __launch_bounds__(256, 1)
void hgemm(const __half* __restrict__ A, const __half* __restrict__ B,
           const float* __restrict__ bias, float* __restrict__ C,
           int Ncols, int K)
{
    extern __shared__ __align__(16) char smem[];
    const uint32_t sb = smem_u32(smem);

    const int tid   = threadIdx.x;
    const int lane  = tid & 31;
    const int warp  = tid >> 5;
    const int warpM = warp >> 2;
    const int warpN = warp & 3;
    const int g     = lane >> 2;
    const int tig   = lane & 3;

    const __half* Aptr = A + (size_t)blockIdx.y * 128 * K;
    const __half* Bptr = B + (size_t)blockIdx.x * 256;

    float acc[4][8][4];
    #pragma unroll
    for (int i = 0; i < 4; i++)
        #pragma unroll
        for (int j = 0; j < 8; j++)
            #pragma unroll
            for (int l = 0; l < 4; l++) acc[i][j][l] = 0.f;

    auto issue = [&](int kt, int s) {
        const uint32_t aB = sb + s * STAGE_SZ;
        const uint32_t bB = aB + STAGE_A;
        #pragma unroll
        for (int it = 0; it < 2; it++) {
            int id = tid + it * 256;
            int r = id >> 2, kc = (id & 3) << 3;
            int R = r >> 1;
            int off = ((r & 1) << 6) | (kc << 1);
            uint32_t dst = aB + R * 128 + (off ^ ((R & 7) << 4));
            const __half* src = Aptr + (size_t)r * K + kt * BKH + kc;
            asm volatile("cp.async.cg.shared.global [%0], [%1], 16;" :: "r"(dst), "l"(src));
        }
        #pragma unroll
        for (int it = 0; it < 4; it++) {
            int id = tid + it * 256;
            int kr = id >> 5, nc = (id & 31) << 3;
            uint32_t dst = bB + kr * 512 + ((nc << 1) ^ ((kr & 7) << 4));
            const __half* src = Bptr + (size_t)(kt * BKH + kr) * Ncols + nc;
            asm volatile("cp.async.cg.shared.global [%0], [%1], 16;" :: "r"(dst), "l"(src));
        }
    };

    auto compute = [&](int s) {
        const uint32_t a_base = sb + s * STAGE_SZ;
        const uint32_t b_base = a_base + STAGE_A;
        #pragma unroll
        for (int ks = 0; ks < 2; ks++) {
            uint32_t af[4][4], bf[8][2];
            #pragma unroll
            for (int mi = 0; mi < 4; mi++) {
                int r = warpM * 64 + mi * 16 + (lane & 15);
                int k = ks * 16 + ((lane >> 4) << 3);
                int R = r >> 1;
                int off = ((r & 1) << 6) | (k << 1);
                uint32_t addr = a_base + R * 128 + (off ^ ((R & 7) << 4));
                asm volatile(
                    "ldmatrix.sync.aligned.m8n8.x4.shared.b16 {%0,%1,%2,%3}, [%4];"
                    : "=r"(af[mi][0]), "=r"(af[mi][1]), "=r"(af[mi][2]), "=r"(af[mi][3])
                    : "r"(addr));
            }
            #pragma unroll
            for (int nip = 0; nip < 4; nip++) {
                int k = ks * 16 + (lane & 15);
                int n = warpN * 64 + nip * 16 + ((lane >> 4) << 3);
                uint32_t addr = b_base + k * 512 + ((n << 1) ^ ((k & 7) << 4));
                asm volatile(
                    "ldmatrix.sync.aligned.m8n8.x4.trans.shared.b16 {%0,%1,%2,%3}, [%4];"
                    : "=r"(bf[2 * nip][0]), "=r"(bf[2 * nip][1]),
                      "=r"(bf[2 * nip + 1][0]), "=r"(bf[2 * nip + 1][1])
                    : "r"(addr));
            }
            #pragma unroll
            for (int mi = 0; mi < 4; mi++)
                #pragma unroll
                for (int ni = 0; ni < 8; ni++) {
                    asm volatile(
                        "mma.sync.aligned.m16n8k16.row.col.f32.f16.f16.f32 "
                        "{%0,%1,%2,%3}, {%4,%5,%6,%7}, {%8,%9}, {%0,%1,%2,%3};\n"
                        : "+f"(acc[mi][ni][0]), "+f"(acc[mi][ni][1]),
                          "+f"(acc[mi][ni][2]), "+f"(acc[mi][ni][3])
                        : "r"(af[mi][0]), "r"(af[mi][1]), "r"(af[mi][2]), "r"(af[mi][3]),
                          "r"(bf[ni][0]), "r"(bf[ni][1]));
                }
        }
    };

    const int nTiles = K / BKH;

    #pragma unroll
    for (int s = 0; s < NST - 1; s++) {
        issue(s, s);
        asm volatile("cp.async.commit_group;" ::: "memory");
    }

    for (int t = 0; t < nTiles; t++) {
        asm volatile("cp.async.wait_group %0;" :: "n"(NST - 2) : "memory");
        __syncthreads();
        const int nt = t + NST - 1;
        if (nt < nTiles) issue(nt, nt % NST);
        asm volatile("cp.async.commit_group;" ::: "memory");
        compute(t % NST);
    }

    // epilogue
    #pragma unroll
    for (int mi = 0; mi < 4; mi++) {
        #pragma unroll
        for (int ni = 0; ni < 8; ni++) {
            const int r0 = blockIdx.y * 128 + warpM * 64 + mi * 16 + g;
            const int c0 = blockIdx.x * 256 + warpN * 64 + ni * 8 + 2 * tig;
            #pragma unroll
            for (int hh = 0; hh < 2; hh++) {
                float v0 = acc[mi][ni][hh * 2 + 0];
                float v1 = acc[mi][ni][hh * 2 + 1];
                if (MODE == 1) {
                    if (c0 < 2 * CH)     v0 = (v0 > 0.f) ? (v0 + 1.f) : expf(v0);
                    if (c0 + 1 < 2 * CH) v1 = (v1 > 0.f) ? (v1 + 1.f) : expf(v1);
                } else if (MODE == 2) {
                    v0 += bias[c0]; v1 += bias[c0 + 1];
                }
                *(float2*)(C + (size_t)(r0 + hh * 8) * Ncols + c0) = make_float2(v0, v1);
            }
        }
    }
}

// ================= prep: fp32 -> fp16 (rn) =================================
__global__ __launch_bounds__(256)
void cvt_f16_kernel(const float4* __restrict__ in, uint4* __restrict__ outp, int n8)
{
    int i = blockIdx.x * 256 + threadIdx.x;
    if (i < n8) {
        float4 a = in[2 * i], b = in[2 * i + 1];
        __half2 h0 = __floats2half2_rn(a.x, a.y);
        __half2 h1 = __floats2half2_rn(a.z, a.w);
        __half2 h2 = __floats2half2_rn(b.x, b.y);
        __half2 h3 = __floats2half2_rn(b.z, b.w);
        uint4 o;
        o.x = *reinterpret_cast<uint32_t*>(&h0);
        o.y = *reinterpret_cast<uint32_t*>(&h1);
        o.z = *reinterpret_cast<uint32_t*>(&h2);
        o.w = *reinterpret_cast<uint32_t*>(&h3);
        outp[i] = o;
    }
}

// ================= kv partial + reduce ======================================
__global__ __launch_bounds__(256)
void kv_partial_kernel()
{
    const int bh    = blockIdx.x;
    const int chunk = blockIdx.y;
    const int b = bh / HEADS, h = bh % HEADS;

    __shared__ float ks[32][HD];
    __shared__ float vs[32][HD];

    const int tid = threadIdx.x;
    const int e0 = (tid % 16) * 4;
    const int d0 = (tid / 16) * 4;

    float acc[4][4] = {};
    float sacc[4] = {0.f, 0.f, 0.f, 0.f};

    const float* base = g_qkv + (size_t)b * SEQ * QKVC + h * HD;
    const int nBeg = chunk * (SEQ / KVCHUNKS);
    const int nEnd = nBeg + (SEQ / KVCHUNKS);

    for (int n0 = nBeg; n0 < nEnd; n0 += 32) {
        #pragma unroll
        for (int i = 0; i < 2; i++) {
            int idx = tid + i * 256;
            int r = idx / 16, c4 = idx % 16;
            const float* rowp = base + (size_t)(n0 + r) * QKVC;
            *(float4*)&ks[r][c4 * 4] = *(const float4*)(rowp + CH     + c4 * 4);
            *(float4*)&vs[r][c4 * 4] = *(const float4*)(rowp + 2 * CH + c4 * 4);
        }
        __syncthreads();
        #pragma unroll 4
        for (int nn = 0; nn < 32; nn++) {
            float kr[4], vr[4];
            #pragma unroll
            for (int i = 0; i < 4; i++) kr[i] = ks[nn][d0 + i];
            #pragma unroll
            for (int j = 0; j < 4; j++) vr[j] = vs[nn][e0 + j];
            #pragma unroll
            for (int i = 0; i < 4; i++)
                #pragma unroll
                for (int j = 0; j < 4; j++)
                    acc[i][j] += kr[i] * vr[j];
            if (e0 == 0) {
                #pragma unroll
                for (int i = 0; i < 4; i++) sacc[i] += kr[i];
            }
        }
        __syncthreads();
    }

    float* kvp = g_kvp + ((size_t)chunk * BH + bh) * HD * HD;
    #pragma unroll
    for (int i = 0; i < 4; i++)
        *(float4*)&kvp[(d0 + i) * HD + e0] =
            make_float4(acc[i][0], acc[i][1], acc[i][2], acc[i][3]);
    if (e0 == 0) {
        #pragma unroll
        for (int i = 0; i < 4; i++)
            g_sumkp[((size_t)chunk * BH + bh) * HD + d0 + i] = sacc[i];
    }
}

__global__ __launch_bounds__(256)
void kv_reduce_kernel()
{
    const int bh = blockIdx.x;
    const int tid = threadIdx.x;
    for (int i = tid; i < HD * HD; i += 256) {
        float s = 0.f;
        #pragma unroll
        for (int c = 0; c < KVCHUNKS; c++)
            s += g_kvp[((size_t)c * BH + bh) * HD * HD + i];
        g_kvh[(size_t)bh * HD * HD + i] = __float2half_rn(s);
    }
    if (tid < HD) {
        float s = 0.f;
        #pragma unroll
        for (int c = 0; c < KVCHUNKS; c++)
            s += g_sumkp[((size_t)c * BH + bh) * HD + tid];
        g_sumk[(size_t)bh * HD + tid] = s;
    }
}

// ================= y via tensor cores: y = (q @ kv) / (q . sumk) ===========
// grid (SEQ/128, BH), 128 threads = 4 warps. M=128, N=64, K=64.
// Warp w: rows w*32..w*32+31 (mi=2), all 64 cols (ni=8), 4 ksteps.
// smem rows are 128B (64 halves); 16B chunk c swizzled: c ^= (row&7).
__global__ __launch_bounds__(128)
void y_mma_kernel()
{
    __shared__ __align__(16) __half qs[128 * 64];   // 16KB
    __shared__ __align__(16) __half kvs[64 * 64];   // 8KB
    __shared__ float sumkS[HD];
    __shared__ float denomS[128];

    const int tid  = threadIdx.x;
    const int lane = tid & 31;
    const int warp = tid >> 5;
    const int bh   = blockIdx.y;
    const int b    = bh / HEADS, h = bh % HEADS;
    const int n0   = blockIdx.x * 128;

    const float* qg = g_qkv + ((size_t)b * SEQ + n0) * QKVC + h * HD;

    // load q (fp32 -> fp16, swizzled): 1024 16B-chunks
    #pragma unroll
    for (int it = 0; it < 8; it++) {
        int id = tid + it * 128;
        int r = id >> 3, c = id & 7;
        const float4* p = (const float4*)(qg + (size_t)r * QKVC + c * 8);
        float4 a = p[0], bb = p[1];
        __half2 h0 = __floats2half2_rn(a.x, a.y);
        __half2 h1 = __floats2half2_rn(a.z, a.w);
        __half2 h2 = __floats2half2_rn(bb.x, bb.y);
        __half2 h3 = __floats2half2_rn(bb.z, bb.w);
        uint4 o;
        o.x = *reinterpret_cast<uint32_t*>(&h0);
        o.y = *reinterpret_cast<uint32_t*>(&h1);
        o.z = *reinterpret_cast<uint32_t*>(&h2);
        o.w = *reinterpret_cast<uint32_t*>(&h3);
        *(uint4*)((char*)qs + r * 128 + (((c ^ (r & 7))) << 4)) = o;
    }
    // load kv fp16 (swizzled): 512 chunks
    const __half* kvg = g_kvh + (size_t)bh * HD * HD;
    #pragma unroll
    for (int it = 0; it < 4; it++) {
        int id = tid + it * 128;
        int d = id >> 3, c = id & 7;
        uint4 o = *(const uint4*)(kvg + d * HD + c * 8);
        *(uint4*)((char*)kvs + d * 128 + (((c ^ (d & 7))) << 4)) = o;
    }
    if (tid < HD) sumkS[tid] = g_sumk[(size_t)bh * HD + tid];
    __syncthreads();

    // denominator (fp32, per row)
    {
        const float* qr = qg + (size_t)tid * QKVC;
        float s = 0.f;
        #pragma unroll
        for (int d = 0; d < HD; d += 4) {
            float4 t = *(const float4*)(qr + d);
            s += t.x * sumkS[d] + t.y * sumkS[d + 1] + t.z * sumkS[d + 2] + t.w * sumkS[d + 3];
        }
        denomS[tid] = 1.0f / s;
    }

    const uint32_t qb = smem_u32(qs);
    const uint32_t kb = smem_u32(kvs);

    float acc[2][8][4];
    #pragma unroll
    for (int i = 0; i < 2; i++)
        #pragma unroll
        for (int j = 0; j < 8; j++)
            #pragma unroll
            for (int l = 0; l < 4; l++) acc[i][j][l] = 0.f;

    #pragma unroll
    for (int ks = 0; ks < 4; ks++) {
        uint32_t af[2][4], bf[8][2];
        #pragma unroll
        for (int mi = 0; mi < 2; mi++) {
            int r = warp * 32 + mi * 16 + (lane & 15);
            int k = ks * 16 + ((lane >> 4) << 3);
            int c = k >> 3;
            uint32_t addr = qb + r * 128 + (((c ^ (r & 7))) << 4);
            asm volatile(
                "ldmatrix.sync.aligned.m8n8.x4.shared.b16 {%0,%1,%2,%3}, [%4];"
                : "=r"(af[mi][0]), "=r"(af[mi][1]), "=r"(af[mi][2]), "=r"(af[mi][3])
                : "r"(addr));
        }
        #pragma unroll
        for (int nip = 0; nip < 4; nip++) {
            int k = ks * 16 + (lane & 15);
            int n = nip * 16 + ((lane >> 4) << 3);
            int c = n >> 3;
            uint32_t addr = kb + k * 128 + (((c ^ (k & 7))) << 4);
            asm volatile(
                "ldmatrix.sync.aligned.m8n8.x4.trans.shared.b16 {%0,%1,%2,%3}, [%4];"
                : "=r"(bf[2 * nip][0]), "=r"(bf[2 * nip][1]),
                  "=r"(bf[2 * nip + 1][0]), "=r"(bf[2 * nip + 1][1])
                : "r"(addr));
        }
        #pragma unroll
        for (int mi = 0; mi < 2; mi++)
            #pragma unroll
            for (int ni = 0; ni < 8; ni++) {
                asm volatile(
                    "mma.sync.aligned.m16n8k16.row.col.f32.f16.f16.f32 "
                    "{%0,%1,%2,%3}, {%4,%5,%6,%7}, {%8,%9}, {%0,%1,%2,%3};\n"
                    : "+f"(acc[mi][ni][0]), "+f"(acc[mi][ni][1]),
                      "+f"(acc[mi][ni][2]), "+f"(acc[mi][ni][3])
                    : "r"(af[mi][0]), "r"(af[mi][1]), "r"(af[mi][2]), "r"(af[mi][3]),
                      "r"(bf[ni][0]), "r"(bf[ni][1]));
            }
    }

    __syncwarp();

    const int g = lane >> 2, tig = lane & 3;
    #pragma unroll
    for (int mi = 0; mi < 2; mi++) {
        #pragma unroll
        for (int hh = 0; hh < 2; hh++) {
            const int rl = warp * 32 + mi * 16 + g + hh * 8;
            const float inv = denomS[rl];
            __half* yrow = g_yh + ((size_t)b * SEQ + n0 + rl) * CH + h * HD;
            #pragma unroll
            for (int ni = 0; ni < 8; ni++) {
                const int col = ni * 8 + 2 * tig;
                __half2 p = __floats2half2_rn(acc[mi][ni][hh * 2 + 0] * inv,
                                              acc[mi][ni][hh * 2 + 1] * inv);
                *(__half2*)(yrow + col) = p;
            }
        }
    }
}

// ---------------------------------------------------------------------------
extern "C" void kernel_launch(void* const* d_in, const int* in_sizes, int n_in,
                              void* d_out, int out_size)
{
    const float* x      = (const float*)d_in[0];
    const float* w_qkv  = (const float*)d_in[1];
    const float* w_proj = (const float*)d_in[2];
    const float* b_proj = (const float*)d_in[3];
    float* out = (float*)d_out;

    float *qkv_p;
    __half *xh_p, *wqkvh_p, *wprojh_p, *yh_p;
    cudaGetSymbolAddress((void**)&qkv_p,    g_qkv);
    cudaGetSymbolAddress((void**)&xh_p,     g_xh);
    cudaGetSymbolAddress((void**)&wqkvh_p,  g_wqkvh);
    cudaGetSymbolAddress((void**)&wprojh_p, g_wprojh);
    cudaGetSymbolAddress((void**)&yh_p,     g_yh);

    cudaFuncSetAttribute(hgemm<1>, cudaFuncAttributeMaxDynamicSharedMemorySize, HG_SMEM);
    cudaFuncSetAttribute(hgemm<2>, cudaFuncAttributeMaxDynamicSharedMemorySize, HG_SMEM);

    // 0) convert inputs to fp16 (rn)
    cvt_f16_kernel<<<(ROWS * CH / 8 + 255) / 256, 256>>>(
        (const float4*)x, (uint4*)xh_p, ROWS * CH / 8);
    cvt_f16_kernel<<<(CH * QKVC / 8 + 255) / 256, 256>>>(
        (const float4*)w_qkv, (uint4*)wqkvh_p, CH * QKVC / 8);
    cvt_f16_kernel<<<(CH * CH / 8 + 255) / 256, 256>>>(
        (const float4*)w_proj, (uint4*)wprojh_p, CH * CH / 8);

    // 1) qkv = x @ w_qkv (fp16 TC, cp.async pipeline), elu+1 fused on q,k
    {
        dim3 grid(QKVC / 256, ROWS / 128);
        hgemm<1><<<grid, 256, HG_SMEM>>>(xh_p, wqkvh_p, nullptr, qkv_p, QKVC, CH);
    }
    // 2) kv outer product (seq-split) + reduce (emits fp16 kv)
    {
        dim3 grid(BH, KVCHUNKS);
        kv_partial_kernel<<<grid, 256>>>();
        kv_reduce_kernel<<<BH, 256>>>();
    }
    // 3) y = (q @ kv) / (q . sumk) on tensor cores, emits fp16
    {
        dim3 grid(SEQ / 128, BH);
        y_mma_kernel<<<grid, 128>>>();
    }
    // 4) out = y @ w_proj + b_proj (fp16 TC, cp.async pipeline)
    {
        dim3 grid(CH / 256, ROWS / 128);
        hgemm<2><<<grid, 256, HG_SMEM>>>(yh_p, wprojh_p, b_proj, out, CH, CH);
    }
}

// round 8
// speedup vs baseline: 5.4606x; 1.0315x over previous
#include <cuda_runtime.h>
#include <cuda_fp16.h>
#include <math.h>
#include <stdint.h>

// Problem constants: B=4, N=4096, C=1024, H=16, D=64
#define BATCH 4
#define SEQ   4096
#define CH    1024
#define HEADS 16
#define HD    64
#define ROWS  (BATCH*SEQ)        // 16384
#define QKVC  (3*CH)             // 3072
#define BH    (BATCH*HEADS)      // 64
#define KVCHUNKS 8

// ---------------- scratch (device globals: allocation-free) ----------------
__device__ float g_qkv [(size_t)ROWS * QKVC];          // GEMM1 out fp32 (elu+1 on q,k)
__device__ __align__(256) __half g_xh    [(size_t)ROWS * CH];
__device__ __align__(256) __half g_wqkvh [(size_t)CH * QKVC];
__device__ __align__(256) __half g_wprojh[(size_t)CH * CH];
__device__ __align__(256) __half g_yh    [(size_t)ROWS * CH];
__device__ __align__(256) __half g_kvh   [(size_t)BH * HD * HD];
__device__ float g_sumk [(size_t)BH * HD];
__device__ float g_kvp  [(size_t)KVCHUNKS * BH * HD * HD];
__device__ float g_sumkp[(size_t)KVCHUNKS * BH * HD];

__device__ __forceinline__ uint32_t smem_u32(const void* p) {
    uint32_t a;
    asm("{ .reg .u64 t; cvta.to.shared.u64 t, %1; cvt.u32.u64 %0, t; }" : "=r"(a) : "l"(p));
    return a;
}

// ================= fp16 GEMM, cp.async 4-stage, 512 threads ================
// Block 128x256, BK=32, 16 warps (4x4), warp tile 32x64, mma.m16n8k16.
// A smem: 128B atoms (2 rows x 32 halves), XOR swizzle. B smem: 512B rows,
// XOR swizzle by k&7. Dynamic smem: 4 stages x 24KB = 96KB.
#define BKH 32
#define NST 4
#define STAGE_A (128 * BKH * 2)            // 8192 B
#define STAGE_B (BKH * 256 * 2)            // 16384 B
#define STAGE_SZ (STAGE_A + STAGE_B)       // 24576 B
#define HG_SMEM (NST * STAGE_SZ)           // 98304 B

template <int MODE>
__global__ __launch_bounds__(512, 1)
void hgemm(const __half* __restrict__ A, const __half* __restrict__ B,
           const float* __restrict__ bias, float* __restrict__ C,
           int Ncols, int K)
{
    extern __shared__ __align__(16) char smem[];
    const uint32_t sb = smem_u32(smem);

    const int tid   = threadIdx.x;
    const int lane  = tid & 31;
    const int warp  = tid >> 5;      // 0..15
    const int warpM = warp >> 2;     // 0..3  (32-row strips)
    const int warpN = warp & 3;      // 0..3  (64-col strips)
    const int g     = lane >> 2;
    const int tig   = lane & 3;

    const __half* Aptr = A + (size_t)blockIdx.y * 128 * K;
    const __half* Bptr = B + (size_t)blockIdx.x * 256;

    float acc[2][8][4];
    #pragma unroll
    for (int i = 0; i < 2; i++)
        #pragma unroll
        for (int j = 0; j < 8; j++)
            #pragma unroll
            for (int l = 0; l < 4; l++) acc[i][j][l] = 0.f;

    auto issue = [&](int kt, int s) {
        const uint32_t aB = sb + s * STAGE_SZ;
        const uint32_t bB = aB + STAGE_A;
        {   // A: 512 chunks, 1 per thread
            int r = tid >> 2, kc = (tid & 3) << 3;
            int R = r >> 1;
            int off = ((r & 1) << 6) | (kc << 1);
            uint32_t dst = aB + R * 128 + (off ^ ((R & 7) << 4));
            const __half* src = Aptr + (size_t)r * K + kt * BKH + kc;
            asm volatile("cp.async.cg.shared.global [%0], [%1], 16;" :: "r"(dst), "l"(src));
        }
        #pragma unroll
        for (int it = 0; it < 2; it++) {   // B: 1024 chunks, 2 per thread
            int id = tid + it * 512;
            int kr = id >> 5, nc = (id & 31) << 3;
            uint32_t dst = bB + kr * 512 + ((nc << 1) ^ ((kr & 7) << 4));
            const __half* src = Bptr + (size_t)(kt * BKH + kr) * Ncols + nc;
            asm volatile("cp.async.cg.shared.global [%0], [%1], 16;" :: "r"(dst), "l"(src));
        }
    };

    auto compute = [&](int s) {
        const uint32_t a_base = sb + s * STAGE_SZ;
        const uint32_t b_base = a_base + STAGE_A;
        #pragma unroll
        for (int ks = 0; ks < 2; ks++) {
            uint32_t af[2][4], bf[8][2];
            #pragma unroll
            for (int mi = 0; mi < 2; mi++) {
                int r = warpM * 32 + mi * 16 + (lane & 15);
                int k = ks * 16 + ((lane >> 4) << 3);
                int R = r >> 1;
                int off = ((r & 1) << 6) | (k << 1);
                uint32_t addr = a_base + R * 128 + (off ^ ((R & 7) << 4));
                asm volatile(
                    "ldmatrix.sync.aligned.m8n8.x4.shared.b16 {%0,%1,%2,%3}, [%4];"
                    : "=r"(af[mi][0]), "=r"(af[mi][1]), "=r"(af[mi][2]), "=r"(af[mi][3])
                    : "r"(addr));
            }
            #pragma unroll
            for (int nip = 0; nip < 4; nip++) {
                int k = ks * 16 + (lane & 15);
                int n = warpN * 64 + nip * 16 + ((lane >> 4) << 3);
                uint32_t addr = b_base + k * 512 + ((n << 1) ^ ((k & 7) << 4));
                asm volatile(
                    "ldmatrix.sync.aligned.m8n8.x4.trans.shared.b16 {%0,%1,%2,%3}, [%4];"
                    : "=r"(bf[2 * nip][0]), "=r"(bf[2 * nip][1]),
                      "=r"(bf[2 * nip + 1][0]), "=r"(bf[2 * nip + 1][1])
                    : "r"(addr));
            }
            #pragma unroll
            for (int mi = 0; mi < 2; mi++)
                #pragma unroll
                for (int ni = 0; ni < 8; ni++) {
                    asm volatile(
                        "mma.sync.aligned.m16n8k16.row.col.f32.f16.f16.f32 "
                        "{%0,%1,%2,%3}, {%4,%5,%6,%7}, {%8,%9}, {%0,%1,%2,%3};\n"
                        : "+f"(acc[mi][ni][0]), "+f"(acc[mi][ni][1]),
                          "+f"(acc[mi][ni][2]), "+f"(acc[mi][ni][3])
                        : "r"(af[mi][0]), "r"(af[mi][1]), "r"(af[mi][2]), "r"(af[mi][3]),
                          "r"(bf[ni][0]), "r"(bf[ni][1]));
                }
        }
    };

    const int nTiles = K / BKH;

    #pragma unroll
    for (int s = 0; s < NST - 1; s++) {
        issue(s, s);
        asm volatile("cp.async.commit_group;" ::: "memory");
    }

    for (int t = 0; t < nTiles; t++) {
        asm volatile("cp.async.wait_group %0;" :: "n"(NST - 2) : "memory");
        __syncthreads();
        const int nt = t + NST - 1;
        if (nt < nTiles) issue(nt, nt % NST);
        asm volatile("cp.async.commit_group;" ::: "memory");
        compute(t % NST);
    }

    // epilogue
    #pragma unroll
    for (int mi = 0; mi < 2; mi++) {
        #pragma unroll
        for (int ni = 0; ni < 8; ni++) {
            const int r0 = blockIdx.y * 128 + warpM * 32 + mi * 16 + g;
            const int c0 = blockIdx.x * 256 + warpN * 64 + ni * 8 + 2 * tig;
            #pragma unroll
            for (int hh = 0; hh < 2; hh++) {
                float v0 = acc[mi][ni][hh * 2 + 0];
                float v1 = acc[mi][ni][hh * 2 + 1];
                if (MODE == 1) {
                    if (c0 < 2 * CH)     v0 = (v0 > 0.f) ? (v0 + 1.f) : expf(v0);
                    if (c0 + 1 < 2 * CH) v1 = (v1 > 0.f) ? (v1 + 1.f) : expf(v1);
                } else if (MODE == 2) {
                    v0 += bias[c0]; v1 += bias[c0 + 1];
                }
                *(float2*)(C + (size_t)(r0 + hh * 8) * Ncols + c0) = make_float2(v0, v1);
            }
        }
    }
}

// ================= prep: fp32 -> fp16 (rn) =================================
__global__ __launch_bounds__(256)
void cvt_f16_kernel(const float4* __restrict__ in, uint4* __restrict__ outp, int n8)
{
    int i = blockIdx.x * 256 + threadIdx.x;
    if (i < n8) {
        float4 a = in[2 * i], b = in[2 * i + 1];
        __half2 h0 = __floats2half2_rn(a.x, a.y);
        __half2 h1 = __floats2half2_rn(a.z, a.w);
        __half2 h2 = __floats2half2_rn(b.x, b.y);
        __half2 h3 = __floats2half2_rn(b.z, b.w);
        uint4 o;
        o.x = *reinterpret_cast<uint32_t*>(&h0);
        o.y = *reinterpret_cast<uint32_t*>(&h1);
        o.z = *reinterpret_cast<uint32_t*>(&h2);
        o.w = *reinterpret_cast<uint32_t*>(&h3);
        outp[i] = o;
    }
}

// ================= kv partial + reduce ======================================
__global__ __launch_bounds__(256)
void kv_partial_kernel()
{
    const int bh    = blockIdx.x;
    const int chunk = blockIdx.y;
    const int b = bh / HEADS, h = bh % HEADS;

    __shared__ float ks[32][HD];
    __shared__ float vs[32][HD];

    const int tid = threadIdx.x;
    const int e0 = (tid % 16) * 4;
    const int d0 = (tid / 16) * 4;

    float acc[4][4] = {};
    float sacc[4] = {0.f, 0.f, 0.f, 0.f};

    const float* base = g_qkv + (size_t)b * SEQ * QKVC + h * HD;
    const int nBeg = chunk * (SEQ / KVCHUNKS);
    const int nEnd = nBeg + (SEQ / KVCHUNKS);

    for (int n0 = nBeg; n0 < nEnd; n0 += 32) {
        #pragma unroll
        for (int i = 0; i < 2; i++) {
            int idx = tid + i * 256;
            int r = idx / 16, c4 = idx % 16;
            const float* rowp = base + (size_t)(n0 + r) * QKVC;
            *(float4*)&ks[r][c4 * 4] = *(const float4*)(rowp + CH     + c4 * 4);
            *(float4*)&vs[r][c4 * 4] = *(const float4*)(rowp + 2 * CH + c4 * 4);
        }
        __syncthreads();
        #pragma unroll 4
        for (int nn = 0; nn < 32; nn++) {
            float kr[4], vr[4];
            #pragma unroll
            for (int i = 0; i < 4; i++) kr[i] = ks[nn][d0 + i];
            #pragma unroll
            for (int j = 0; j < 4; j++) vr[j] = vs[nn][e0 + j];
            #pragma unroll
            for (int i = 0; i < 4; i++)
                #pragma unroll
                for (int j = 0; j < 4; j++)
                    acc[i][j] += kr[i] * vr[j];
            if (e0 == 0) {
                #pragma unroll
                for (int i = 0; i < 4; i++) sacc[i] += kr[i];
            }
        }
        __syncthreads();
    }

    float* kvp = g_kvp + ((size_t)chunk * BH + bh) * HD * HD;
    #pragma unroll
    for (int i = 0; i < 4; i++)
        *(float4*)&kvp[(d0 + i) * HD + e0] =
            make_float4(acc[i][0], acc[i][1], acc[i][2], acc[i][3]);
    if (e0 == 0) {
        #pragma unroll
        for (int i = 0; i < 4; i++)
            g_sumkp[((size_t)chunk * BH + bh) * HD + d0 + i] = sacc[i];
    }
}

__global__ __launch_bounds__(256)
void kv_reduce_kernel()
{
    const int bh = blockIdx.x;
    const int tid = threadIdx.x;
    for (int i = tid; i < HD * HD; i += 256) {
        float s = 0.f;
        #pragma unroll
        for (int c = 0; c < KVCHUNKS; c++)
            s += g_kvp[((size_t)c * BH + bh) * HD * HD + i];
        g_kvh[(size_t)bh * HD * HD + i] = __float2half_rn(s);
    }
    if (tid < HD) {
        float s = 0.f;
        #pragma unroll
        for (int c = 0; c < KVCHUNKS; c++)
            s += g_sumkp[((size_t)c * BH + bh) * HD + tid];
        g_sumk[(size_t)bh * HD + tid] = s;
    }
}

// ================= y via tensor cores: y = (q @ kv) / (q . sumk) ===========
__global__ __launch_bounds__(128)
void y_mma_kernel()
{
    __shared__ __align__(16) __half qs[128 * 64];
    __shared__ __align__(16) __half kvs[64 * 64];
    __shared__ float sumkS[HD];
    __shared__ float denomS[128];

    const int tid  = threadIdx.x;
    const int lane = tid & 31;
    const int warp = tid >> 5;
    const int bh   = blockIdx.y;
    const int b    = bh / HEADS, h = bh % HEADS;
    const int n0   = blockIdx.x * 128;

    const float* qg = g_qkv + ((size_t)b * SEQ + n0) * QKVC + h * HD;

    #pragma unroll
    for (int it = 0; it < 8; it++) {
        int id = tid + it * 128;
        int r = id >> 3, c = id & 7;
        const float4* p = (const float4*)(qg + (size_t)r * QKVC + c * 8);
        float4 a = p[0], bb = p[1];
        __half2 h0 = __floats2half2_rn(a.x, a.y);
        __half2 h1 = __floats2half2_rn(a.z, a.w);
        __half2 h2 = __floats2half2_rn(bb.x, bb.y);
        __half2 h3 = __floats2half2_rn(bb.z, bb.w);
        uint4 o;
        o.x = *reinterpret_cast<uint32_t*>(&h0);
        o.y = *reinterpret_cast<uint32_t*>(&h1);
        o.z = *reinterpret_cast<uint32_t*>(&h2);
        o.w = *reinterpret_cast<uint32_t*>(&h3);
        *(uint4*)((char*)qs + r * 128 + (((c ^ (r & 7))) << 4)) = o;
    }
    const __half* kvg = g_kvh + (size_t)bh * HD * HD;
    #pragma unroll
    for (int it = 0; it < 4; it++) {
        int id = tid + it * 128;
        int d = id >> 3, c = id & 7;
        uint4 o = *(const uint4*)(kvg + d * HD + c * 8);
        *(uint4*)((char*)kvs + d * 128 + (((c ^ (d & 7))) << 4)) = o;
    }
    if (tid < HD) sumkS[tid] = g_sumk[(size_t)bh * HD + tid];
    __syncthreads();

    {
        const float* qr = qg + (size_t)tid * QKVC;
        float s = 0.f;
        #pragma unroll
        for (int d = 0; d < HD; d += 4) {
            float4 t = *(const float4*)(qr + d);
            s += t.x * sumkS[d] + t.y * sumkS[d + 1] + t.z * sumkS[d + 2] + t.w * sumkS[d + 3];
        }
        denomS[tid] = 1.0f / s;
    }

    const uint32_t qb = smem_u32(qs);
    const uint32_t kb = smem_u32(kvs);

    float acc[2][8][4];
    #pragma unroll
    for (int i = 0; i < 2; i++)
        #pragma unroll
        for (int j = 0; j < 8; j++)
            #pragma unroll
            for (int l = 0; l < 4; l++) acc[i][j][l] = 0.f;

    #pragma unroll
    for (int ks = 0; ks < 4; ks++) {
        uint32_t af[2][4], bf[8][2];
        #pragma unroll
        for (int mi = 0; mi < 2; mi++) {
            int r = warp * 32 + mi * 16 + (lane & 15);
            int k = ks * 16 + ((lane >> 4) << 3);
            int c = k >> 3;
            uint32_t addr = qb + r * 128 + (((c ^ (r & 7))) << 4);
            asm volatile(
                "ldmatrix.sync.aligned.m8n8.x4.shared.b16 {%0,%1,%2,%3}, [%4];"
                : "=r"(af[mi][0]), "=r"(af[mi][1]), "=r"(af[mi][2]), "=r"(af[mi][3])
                : "r"(addr));
        }
        #pragma unroll
        for (int nip = 0; nip < 4; nip++) {
            int k = ks * 16 + (lane & 15);
            int n = nip * 16 + ((lane >> 4) << 3);
            int c = n >> 3;
            uint32_t addr = kb + k * 128 + (((c ^ (k & 7))) << 4);
            asm volatile(
                "ldmatrix.sync.aligned.m8n8.x4.trans.shared.b16 {%0,%1,%2,%3}, [%4];"
                : "=r"(bf[2 * nip][0]), "=r"(bf[2 * nip][1]),
                  "=r"(bf[2 * nip + 1][0]), "=r"(bf[2 * nip + 1][1])
                : "r"(addr));
        }
        #pragma unroll
        for (int mi = 0; mi < 2; mi++)
            #pragma unroll
            for (int ni = 0; ni < 8; ni++) {
                asm volatile(
                    "mma.sync.aligned.m16n8k16.row.col.f32.f16.f16.f32 "
                    "{%0,%1,%2,%3}, {%4,%5,%6,%7}, {%8,%9}, {%0,%1,%2,%3};\n"
                    : "+f"(acc[mi][ni][0]), "+f"(acc[mi][ni][1]),
                      "+f"(acc[mi][ni][2]), "+f"(acc[mi][ni][3])
                    : "r"(af[mi][0]), "r"(af[mi][1]), "r"(af[mi][2]), "r"(af[mi][3]),
                      "r"(bf[ni][0]), "r"(bf[ni][1]));
            }
    }

    __syncwarp();

    const int g = lane >> 2, tig = lane & 3;
    #pragma unroll
    for (int mi = 0; mi < 2; mi++) {
        #pragma unroll
        for (int hh = 0; hh < 2; hh++) {
            const int rl = warp * 32 + mi * 16 + g + hh * 8;
            const float inv = denomS[rl];
            __half* yrow = g_yh + ((size_t)b * SEQ + n0 + rl) * CH + h * HD;
            #pragma unroll
            for (int ni = 0; ni < 8; ni++) {
                const int col = ni * 8 + 2 * tig;
                __half2 p = __floats2half2_rn(acc[mi][ni][hh * 2 + 0] * inv,
                                              acc[mi][ni][hh * 2 + 1] * inv);
                *(__half2*)(yrow + col) = p;
            }
        }
    }
}

// ---------------------------------------------------------------------------
extern "C" void kernel_launch(void* const* d_in, const int* in_sizes, int n_in,
                              void* d_out, int out_size)
{
    const float* x      = (const float*)d_in[0];
    const float* w_qkv  = (const float*)d_in[1];
    const float* w_proj = (const float*)d_in[2];
    const float* b_proj = (const float*)d_in[3];
    float* out = (float*)d_out;

    float *qkv_p;
    __half *xh_p, *wqkvh_p, *wprojh_p, *yh_p;
    cudaGetSymbolAddress((void**)&qkv_p,    g_qkv);
    cudaGetSymbolAddress((void**)&xh_p,     g_xh);
    cudaGetSymbolAddress((void**)&wqkvh_p,  g_wqkvh);
    cudaGetSymbolAddress((void**)&wprojh_p, g_wprojh);
    cudaGetSymbolAddress((void**)&yh_p,     g_yh);

    cudaFuncSetAttribute(hgemm<1>, cudaFuncAttributeMaxDynamicSharedMemorySize, HG_SMEM);
    cudaFuncSetAttribute(hgemm<2>, cudaFuncAttributeMaxDynamicSharedMemorySize, HG_SMEM);

    // 0) convert inputs to fp16 (rn)
    cvt_f16_kernel<<<(ROWS * CH / 8 + 255) / 256, 256>>>(
        (const float4*)x, (uint4*)xh_p, ROWS * CH / 8);
    cvt_f16_kernel<<<(CH * QKVC / 8 + 255) / 256, 256>>>(
        (const float4*)w_qkv, (uint4*)wqkvh_p, CH * QKVC / 8);
    cvt_f16_kernel<<<(CH * CH / 8 + 255) / 256, 256>>>(
        (const float4*)w_proj, (uint4*)wprojh_p, CH * CH / 8);

    // 1) qkv = x @ w_qkv (fp16 TC, 512 thr), elu+1 fused on q,k
    {
        dim3 grid(QKVC / 256, ROWS / 128);
        hgemm<1><<<grid, 512, HG_SMEM>>>(xh_p, wqkvh_p, nullptr, qkv_p, QKVC, CH);
    }
    // 2) kv outer product (seq-split) + reduce (emits fp16 kv)
    {
        dim3 grid(BH, KVCHUNKS);
        kv_partial_kernel<<<grid, 256>>>();
        kv_reduce_kernel<<<BH, 256>>>();
    }
    // 3) y = (q @ kv) / (q . sumk) on tensor cores, emits fp16
    {
        dim3 grid(SEQ / 128, BH);
        y_mma_kernel<<<grid, 128>>>();
    }
    // 4) out = y @ w_proj + b_proj (fp16 TC, 512 thr)
    {
        dim3 grid(CH / 256, ROWS / 128);
        hgemm<2><<<grid, 512, HG_SMEM>>>(yh_p, wprojh_p, b_proj, out, CH, CH);
    }
}

// round 9
// speedup vs baseline: 6.2473x; 1.1441x over previous
#include <cuda_runtime.h>
#include <cuda_fp16.h>
#include <math.h>
#include <stdint.h>

// Problem constants: B=4, N=4096, C=1024, H=16, D=64
#define BATCH 4
#define SEQ   4096
#define CH    1024
#define HEADS 16
#define HD    64
#define ROWS  (BATCH*SEQ)        // 16384
#define QKVC  (3*CH)             // 3072
#define BH    (BATCH*HEADS)      // 64
#define KVCHUNKS 8

// ---------------- scratch (device globals: allocation-free) ----------------
__device__ float g_qkv [(size_t)ROWS * QKVC];          // GEMM1 out fp32 (elu+1 on q,k)
__device__ __align__(256) __half g_xh    [(size_t)ROWS * CH];
__device__ __align__(256) __half g_wqkvh [(size_t)CH * QKVC];
__device__ __align__(256) __half g_wprojh[(size_t)CH * CH];
__device__ __align__(256) __half g_yh    [(size_t)ROWS * CH];
__device__ __align__(256) __half g_kvh   [(size_t)BH * HD * HD];
__device__ float g_sumk [(size_t)BH * HD];
__device__ float g_kvp  [(size_t)KVCHUNKS * BH * HD * HD];
__device__ float g_sumkp[(size_t)KVCHUNKS * BH * HD];

__device__ __forceinline__ uint32_t smem_u32(const void* p) {
    uint32_t a;
    asm("{ .reg .u64 t; cvta.to.shared.u64 t, %1; cvt.u32.u64 %0, t; }" : "=r"(a) : "l"(p));
    return a;
}

// ============ fp16 GEMM, cp.async 3-stage, 256 threads, 2 CTAs/SM ==========
// Block 128x128, BK=64, 8 warps (4x2), warp tile 32x64, mma.m16n8k16.
// A smem: rows of 64 halves (128B), 16B chunk c at (c ^ (r&7)).
// B smem: rows of 128 halves (256B), 16B chunk c at (c ^ (k&7)).
// Dynamic smem: 3 stages x 32KB = 96KB -> 2 CTAs/SM.
#define BKH 64
#define NST 3
#define STAGE_A (128 * BKH * 2)            // 16384 B
#define STAGE_B (BKH * 128 * 2)            // 16384 B
#define STAGE_SZ (STAGE_A + STAGE_B)       // 32768 B
#define HG_SMEM (NST * STAGE_SZ)           // 98304 B

template <int MODE>
__global__ __launch_bounds__(256, 2)
void hgemm(const __half* __restrict__ A, const __half* __restrict__ B,
           const float* __restrict__ bias, float* __restrict__ C,
           int Ncols, int K)
{
    extern __shared__ __align__(16) char smem[];
    const uint32_t sb = smem_u32(smem);

    const int tid   = threadIdx.x;
    const int lane  = tid & 31;
    const int warp  = tid >> 5;      // 0..7
    const int warpM = warp >> 1;     // 0..3  (32-row strips)
    const int warpN = warp & 1;      // 0..1  (64-col strips)
    const int g     = lane >> 2;
    const int tig   = lane & 3;

    const __half* Aptr = A + (size_t)blockIdx.y * 128 * K;
    const __half* Bptr = B + (size_t)blockIdx.x * 128;

    float acc[2][8][4];
    #pragma unroll
    for (int i = 0; i < 2; i++)
        #pragma unroll
        for (int j = 0; j < 8; j++)
            #pragma unroll
            for (int l = 0; l < 4; l++) acc[i][j][l] = 0.f;

    auto issue = [&](int kt, int s) {
        const uint32_t aB = sb + s * STAGE_SZ;
        const uint32_t bB = aB + STAGE_A;
        // A: 128 rows x 8 chunks = 1024 chunks, 4/thread
        #pragma unroll
        for (int it = 0; it < 4; it++) {
            int id = tid + it * 256;
            int r = id >> 3, c = id & 7;
            uint32_t dst = aB + r * 128 + ((c ^ (r & 7)) << 4);
            const __half* src = Aptr + (size_t)r * K + kt * BKH + c * 8;
            asm volatile("cp.async.cg.shared.global [%0], [%1], 16;" :: "r"(dst), "l"(src));
        }
        // B: 64 rows x 16 chunks = 1024 chunks, 4/thread
        #pragma unroll
        for (int it = 0; it < 4; it++) {
            int id = tid + it * 256;
            int kr = id >> 4, c = id & 15;
            uint32_t dst = bB + kr * 256 + ((c ^ (kr & 7)) << 4);
            const __half* src = Bptr + (size_t)(kt * BKH + kr) * Ncols + c * 8;
            asm volatile("cp.async.cg.shared.global [%0], [%1], 16;" :: "r"(dst), "l"(src));
        }
    };

    auto compute = [&](int s) {
        const uint32_t a_base = sb + s * STAGE_SZ;
        const uint32_t b_base = a_base + STAGE_A;
        #pragma unroll
        for (int ks = 0; ks < 4; ks++) {
            uint32_t af[2][4], bf[8][2];
            #pragma unroll
            for (int mi = 0; mi < 2; mi++) {
                int r = warpM * 32 + mi * 16 + (lane & 15);
                int k = ks * 16 + ((lane >> 4) << 3);
                int c = k >> 3;
                uint32_t addr = a_base + r * 128 + ((c ^ (r & 7)) << 4);
                asm volatile(
                    "ldmatrix.sync.aligned.m8n8.x4.shared.b16 {%0,%1,%2,%3}, [%4];"
                    : "=r"(af[mi][0]), "=r"(af[mi][1]), "=r"(af[mi][2]), "=r"(af[mi][3])
                    : "r"(addr));
            }
            #pragma unroll
            for (int nip = 0; nip < 4; nip++) {
                int k = ks * 16 + (lane & 15);
                int n = warpN * 64 + nip * 16 + ((lane >> 4) << 3);
                int c = n >> 3;
                uint32_t addr = b_base + k * 256 + ((c ^ (k & 7)) << 4);
                asm volatile(
                    "ldmatrix.sync.aligned.m8n8.x4.trans.shared.b16 {%0,%1,%2,%3}, [%4];"
                    : "=r"(bf[2 * nip][0]), "=r"(bf[2 * nip][1]),
                      "=r"(bf[2 * nip + 1][0]), "=r"(bf[2 * nip + 1][1])
                    : "r"(addr));
            }
            #pragma unroll
            for (int mi = 0; mi < 2; mi++)
                #pragma unroll
                for (int ni = 0; ni < 8; ni++) {
                    asm volatile(
                        "mma.sync.aligned.m16n8k16.row.col.f32.f16.f16.f32 "
                        "{%0,%1,%2,%3}, {%4,%5,%6,%7}, {%8,%9}, {%0,%1,%2,%3};\n"
                        : "+f"(acc[mi][ni][0]), "+f"(acc[mi][ni][1]),
                          "+f"(acc[mi][ni][2]), "+f"(acc[mi][ni][3])
                        : "r"(af[mi][0]), "r"(af[mi][1]), "r"(af[mi][2]), "r"(af[mi][3]),
                          "r"(bf[ni][0]), "r"(bf[ni][1]));
                }
        }
    };

    const int nTiles = K / BKH;

    #pragma unroll
    for (int s = 0; s < NST - 1; s++) {
        issue(s, s);
        asm volatile("cp.async.commit_group;" ::: "memory");
    }

    for (int t = 0; t < nTiles; t++) {
        asm volatile("cp.async.wait_group %0;" :: "n"(NST - 2) : "memory");
        __syncthreads();
        const int nt = t + NST - 1;
        if (nt < nTiles) issue(nt, nt % NST);
        asm volatile("cp.async.commit_group;" ::: "memory");
        compute(t % NST);
    }

    // epilogue
    #pragma unroll
    for (int mi = 0; mi < 2; mi++) {
        #pragma unroll
        for (int ni = 0; ni < 8; ni++) {
            const int r0 = blockIdx.y * 128 + warpM * 32 + mi * 16 + g;
            const int c0 = blockIdx.x * 128 + warpN * 64 + ni * 8 + 2 * tig;
            #pragma unroll
            for (int hh = 0; hh < 2; hh++) {
                float v0 = acc[mi][ni][hh * 2 + 0];
                float v1 = acc[mi][ni][hh * 2 + 1];
                if (MODE == 1) {
                    if (c0 < 2 * CH)     v0 = (v0 > 0.f) ? (v0 + 1.f) : expf(v0);
                    if (c0 + 1 < 2 * CH) v1 = (v1 > 0.f) ? (v1 + 1.f) : expf(v1);
                } else if (MODE == 2) {
                    v0 += bias[c0]; v1 += bias[c0 + 1];
                }
                *(float2*)(C + (size_t)(r0 + hh * 8) * Ncols + c0) = make_float2(v0, v1);
            }
        }
    }
}

// ================= prep: fp32 -> fp16 (rn) =================================
__global__ __launch_bounds__(256)
void cvt_f16_kernel(const float4* __restrict__ in, uint4* __restrict__ outp, int n8)
{
    int i = blockIdx.x * 256 + threadIdx.x;
    if (i < n8) {
        float4 a = in[2 * i], b = in[2 * i + 1];
        __half2 h0 = __floats2half2_rn(a.x, a.y);
        __half2 h1 = __floats2half2_rn(a.z, a.w);
        __half2 h2 = __floats2half2_rn(b.x, b.y);
        __half2 h3 = __floats2half2_rn(b.z, b.w);
        uint4 o;
        o.x = *reinterpret_cast<uint32_t*>(&h0);
        o.y = *reinterpret_cast<uint32_t*>(&h1);
        o.z = *reinterpret_cast<uint32_t*>(&h2);
        o.w = *reinterpret_cast<uint32_t*>(&h3);
        outp[i] = o;
    }
}

// ================= kv partial + reduce ======================================
__global__ __launch_bounds__(256)
void kv_partial_kernel()
{
    const int bh    = blockIdx.x;
    const int chunk = blockIdx.y;
    const int b = bh / HEADS, h = bh % HEADS;

    __shared__ float ks[32][HD];
    __shared__ float vs[32][HD];

    const int tid = threadIdx.x;
    const int e0 = (tid % 16) * 4;
    const int d0 = (tid / 16) * 4;

    float acc[4][4] = {};
    float sacc[4] = {0.f, 0.f, 0.f, 0.f};

    const float* base = g_qkv + (size_t)b * SEQ * QKVC + h * HD;
    const int nBeg = chunk * (SEQ / KVCHUNKS);
    const int nEnd = nBeg + (SEQ / KVCHUNKS);

    for (int n0 = nBeg; n0 < nEnd; n0 += 32) {
        #pragma unroll
        for (int i = 0; i < 2; i++) {
            int idx = tid + i * 256;
            int r = idx / 16, c4 = idx % 16;
            const float* rowp = base + (size_t)(n0 + r) * QKVC;
            *(float4*)&ks[r][c4 * 4] = *(const float4*)(rowp + CH     + c4 * 4);
            *(float4*)&vs[r][c4 * 4] = *(const float4*)(rowp + 2 * CH + c4 * 4);
        }
        __syncthreads();
        #pragma unroll 4
        for (int nn = 0; nn < 32; nn++) {
            float kr[4], vr[4];
            #pragma unroll
            for (int i = 0; i < 4; i++) kr[i] = ks[nn][d0 + i];
            #pragma unroll
            for (int j = 0; j < 4; j++) vr[j] = vs[nn][e0 + j];
            #pragma unroll
            for (int i = 0; i < 4; i++)
                #pragma unroll
                for (int j = 0; j < 4; j++)
                    acc[i][j] += kr[i] * vr[j];
            if (e0 == 0) {
                #pragma unroll
                for (int i = 0; i < 4; i++) sacc[i] += kr[i];
            }
        }
        __syncthreads();
    }

    float* kvp = g_kvp + ((size_t)chunk * BH + bh) * HD * HD;
    #pragma unroll
    for (int i = 0; i < 4; i++)
        *(float4*)&kvp[(d0 + i) * HD + e0] =
            make_float4(acc[i][0], acc[i][1], acc[i][2], acc[i][3]);
    if (e0 == 0) {
        #pragma unroll
        for (int i = 0; i < 4; i++)
            g_sumkp[((size_t)chunk * BH + bh) * HD + d0 + i] = sacc[i];
    }
}

__global__ __launch_bounds__(256)
void kv_reduce_kernel()
{
    const int bh = blockIdx.x;
    const int tid = threadIdx.x;
    for (int i = tid; i < HD * HD; i += 256) {
        float s = 0.f;
        #pragma unroll
        for (int c = 0; c < KVCHUNKS; c++)
            s += g_kvp[((size_t)c * BH + bh) * HD * HD + i];
        g_kvh[(size_t)bh * HD * HD + i] = __float2half_rn(s);
    }
    if (tid < HD) {
        float s = 0.f;
        #pragma unroll
        for (int c = 0; c < KVCHUNKS; c++)
            s += g_sumkp[((size_t)c * BH + bh) * HD + tid];
        g_sumk[(size_t)bh * HD + tid] = s;
    }
}

// ================= y via tensor cores: y = (q @ kv) / (q . sumk) ===========
__global__ __launch_bounds__(128)
void y_mma_kernel()
{
    __shared__ __align__(16) __half qs[128 * 64];
    __shared__ __align__(16) __half kvs[64 * 64];
    __shared__ float sumkS[HD];
    __shared__ float denomS[128];

    const int tid  = threadIdx.x;
    const int lane = tid & 31;
    const int warp = tid >> 5;
    const int bh   = blockIdx.y;
    const int b    = bh / HEADS, h = bh % HEADS;
    const int n0   = blockIdx.x * 128;

    const float* qg = g_qkv + ((size_t)b * SEQ + n0) * QKVC + h * HD;

    #pragma unroll
    for (int it = 0; it < 8; it++) {
        int id = tid + it * 128;
        int r = id >> 3, c = id & 7;
        const float4* p = (const float4*)(qg + (size_t)r * QKVC + c * 8);
        float4 a = p[0], bb = p[1];
        __half2 h0 = __floats2half2_rn(a.x, a.y);
        __half2 h1 = __floats2half2_rn(a.z, a.w);
        __half2 h2 = __floats2half2_rn(bb.x, bb.y);
        __half2 h3 = __floats2half2_rn(bb.z, bb.w);
        uint4 o;
        o.x = *reinterpret_cast<uint32_t*>(&h0);
        o.y = *reinterpret_cast<uint32_t*>(&h1);
        o.z = *reinterpret_cast<uint32_t*>(&h2);
        o.w = *reinterpret_cast<uint32_t*>(&h3);
        *(uint4*)((char*)qs + r * 128 + (((c ^ (r & 7))) << 4)) = o;
    }
    const __half* kvg = g_kvh + (size_t)bh * HD * HD;
    #pragma unroll
    for (int it = 0; it < 4; it++) {
        int id = tid + it * 128;
        int d = id >> 3, c = id & 7;
        uint4 o = *(const uint4*)(kvg + d * HD + c * 8);
        *(uint4*)((char*)kvs + d * 128 + (((c ^ (d & 7))) << 4)) = o;
    }
    if (tid < HD) sumkS[tid] = g_sumk[(size_t)bh * HD + tid];
    __syncthreads();

    {
        const float* qr = qg + (size_t)tid * QKVC;
        float s = 0.f;
        #pragma unroll
        for (int d = 0; d < HD; d += 4) {
            float4 t = *(const float4*)(qr + d);
            s += t.x * sumkS[d] + t.y * sumkS[d + 1] + t.z * sumkS[d + 2] + t.w * sumkS[d + 3];
        }
        denomS[tid] = 1.0f / s;
    }

    const uint32_t qb = smem_u32(qs);
    const uint32_t kb = smem_u32(kvs);

    float acc[2][8][4];
    #pragma unroll
    for (int i = 0; i < 2; i++)
        #pragma unroll
        for (int j = 0; j < 8; j++)
            #pragma unroll
            for (int l = 0; l < 4; l++) acc[i][j][l] = 0.f;

    #pragma unroll
    for (int ks = 0; ks < 4; ks++) {
        uint32_t af[2][4], bf[8][2];
        #pragma unroll
        for (int mi = 0; mi < 2; mi++) {
            int r = warp * 32 + mi * 16 + (lane & 15);
            int k = ks * 16 + ((lane >> 4) << 3);
            int c = k >> 3;
            uint32_t addr = qb + r * 128 + (((c ^ (r & 7))) << 4);
            asm volatile(
                "ldmatrix.sync.aligned.m8n8.x4.shared.b16 {%0,%1,%2,%3}, [%4];"
                : "=r"(af[mi][0]), "=r"(af[mi][1]), "=r"(af[mi][2]), "=r"(af[mi][3])
                : "r"(addr));
        }
        #pragma unroll
        for (int nip = 0; nip < 4; nip++) {
            int k = ks * 16 + (lane & 15);
            int n = nip * 16 + ((lane >> 4) << 3);
            int c = n >> 3;
            uint32_t addr = kb + k * 128 + (((c ^ (k & 7))) << 4);
            asm volatile(
                "ldmatrix.sync.aligned.m8n8.x4.trans.shared.b16 {%0,%1,%2,%3}, [%4];"
                : "=r"(bf[2 * nip][0]), "=r"(bf[2 * nip][1]),
                  "=r"(bf[2 * nip + 1][0]), "=r"(bf[2 * nip + 1][1])
                : "r"(addr));
        }
        #pragma unroll
        for (int mi = 0; mi < 2; mi++)
            #pragma unroll
            for (int ni = 0; ni < 8; ni++) {
                asm volatile(
                    "mma.sync.aligned.m16n8k16.row.col.f32.f16.f16.f32 "
                    "{%0,%1,%2,%3}, {%4,%5,%6,%7}, {%8,%9}, {%0,%1,%2,%3};\n"
                    : "+f"(acc[mi][ni][0]), "+f"(acc[mi][ni][1]),
                      "+f"(acc[mi][ni][2]), "+f"(acc[mi][ni][3])
                    : "r"(af[mi][0]), "r"(af[mi][1]), "r"(af[mi][2]), "r"(af[mi][3]),
                      "r"(bf[ni][0]), "r"(bf[ni][1]));
            }
    }

    __syncwarp();

    const int g = lane >> 2, tig = lane & 3;
    #pragma unroll
    for (int mi = 0; mi < 2; mi++) {
        #pragma unroll
        for (int hh = 0; hh < 2; hh++) {
            const int rl = warp * 32 + mi * 16 + g + hh * 8;
            const float inv = denomS[rl];
            __half* yrow = g_yh + ((size_t)b * SEQ + n0 + rl) * CH + h * HD;
            #pragma unroll
            for (int ni = 0; ni < 8; ni++) {
                const int col = ni * 8 + 2 * tig;
                __half2 p = __floats2half2_rn(acc[mi][ni][hh * 2 + 0] * inv,
                                              acc[mi][ni][hh * 2 + 1] * inv);
                *(__half2*)(yrow + col) = p;
            }
        }
    }
}

// ---------------------------------------------------------------------------
extern "C" void kernel_launch(void* const* d_in, const int* in_sizes, int n_in,
                              void* d_out, int out_size)
{
    const float* x      = (const float*)d_in[0];
    const float* w_qkv  = (const float*)d_in[1];
    const float* w_proj = (const float*)d_in[2];
    const float* b_proj = (const float*)d_in[3];
    float* out = (float*)d_out;

    float *qkv_p;
    __half *xh_p, *wqkvh_p, *wprojh_p, *yh_p;
    cudaGetSymbolAddress((void**)&qkv_p,    g_qkv);
    cudaGetSymbolAddress((void**)&xh_p,     g_xh);
    cudaGetSymbolAddress((void**)&wqkvh_p,  g_wqkvh);
    cudaGetSymbolAddress((void**)&wprojh_p, g_wprojh);
    cudaGetSymbolAddress((void**)&yh_p,     g_yh);

    cudaFuncSetAttribute(hgemm<1>, cudaFuncAttributeMaxDynamicSharedMemorySize, HG_SMEM);
    cudaFuncSetAttribute(hgemm<2>, cudaFuncAttributeMaxDynamicSharedMemorySize, HG_SMEM);

    // 0) convert inputs to fp16 (rn)
    cvt_f16_kernel<<<(ROWS * CH / 8 + 255) / 256, 256>>>(
        (const float4*)x, (uint4*)xh_p, ROWS * CH / 8);
    cvt_f16_kernel<<<(CH * QKVC / 8 + 255) / 256, 256>>>(
        (const float4*)w_qkv, (uint4*)wqkvh_p, CH * QKVC / 8);
    cvt_f16_kernel<<<(CH * CH / 8 + 255) / 256, 256>>>(
        (const float4*)w_proj, (uint4*)wprojh_p, CH * CH / 8);

    // 1) qkv = x @ w_qkv (fp16 TC, 2 CTAs/SM), elu+1 fused on q,k
    {
        dim3 grid(QKVC / 128, ROWS / 128);
        hgemm<1><<<grid, 256, HG_SMEM>>>(xh_p, wqkvh_p, nullptr, qkv_p, QKVC, CH);
    }
    // 2) kv outer product (seq-split) + reduce (emits fp16 kv)
    {
        dim3 grid(BH, KVCHUNKS);
        kv_partial_kernel<<<grid, 256>>>();
        kv_reduce_kernel<<<BH, 256>>>();
    }
    // 3) y = (q @ kv) / (q . sumk) on tensor cores, emits fp16
    {
        dim3 grid(SEQ / 128, BH);
        y_mma_kernel<<<grid, 128>>>();
    }
    // 4) out = y @ w_proj + b_proj (fp16 TC, 2 CTAs/SM)
    {
        dim3 grid(CH / 128, ROWS / 128);
        hgemm<2><<<grid, 256, HG_SMEM>>>(yh_p, wprojh_p, b_proj, out, CH, CH);
    }
}

// round 10
// speedup vs baseline: 6.2494x; 1.0003x over previous
#include <cuda_runtime.h>
#include <cuda_fp16.h>
#include <math.h>
#include <stdint.h>

// Problem constants: B=4, N=4096, C=1024, H=16, D=64
#define BATCH 4
#define SEQ   4096
#define CH    1024
#define HEADS 16
#define HD    64
#define ROWS  (BATCH*SEQ)        // 16384
#define QKVC  (3*CH)             // 3072
#define BH    (BATCH*HEADS)      // 64
#define KVCHUNKS 8

// ---------------- scratch (device globals: allocation-free) ----------------
__device__ __align__(256) __half g_qkvh  [(size_t)ROWS * QKVC];  // qkv fp16 (elu+1 on q,k)
__device__ __align__(256) __half g_xh    [(size_t)ROWS * CH];
__device__ __align__(256) __half g_wqkvh [(size_t)CH * QKVC];
__device__ __align__(256) __half g_wprojh[(size_t)CH * CH];
__device__ __align__(256) __half g_yh    [(size_t)ROWS * CH];
__device__ __align__(256) __half g_kvh   [(size_t)BH * HD * HD];
__device__ float g_sumk [(size_t)BH * HD];
__device__ float g_kvp  [(size_t)KVCHUNKS * BH * HD * HD];
__device__ float g_sumkp[(size_t)KVCHUNKS * BH * HD];

__device__ __forceinline__ uint32_t smem_u32(const void* p) {
    uint32_t a;
    asm("{ .reg .u64 t; cvta.to.shared.u64 t, %1; cvt.u32.u64 %0, t; }" : "=r"(a) : "l"(p));
    return a;
}

// ============ fp16 GEMM, cp.async 3-stage, 256 threads, 2 CTAs/SM ==========
// Block 128x128, BK=64, 8 warps (4x2), warp tile 32x64, mma.m16n8k16.
// MODE 1: elu+1 on cols < 2048, output fp16. MODE 2: +bias, output fp32.
#define BKH 64
#define NST 3
#define STAGE_A (128 * BKH * 2)            // 16384 B
#define STAGE_B (BKH * 128 * 2)            // 16384 B
#define STAGE_SZ (STAGE_A + STAGE_B)       // 32768 B
#define HG_SMEM (NST * STAGE_SZ)           // 98304 B

template <int MODE>
__global__ __launch_bounds__(256, 2)
void hgemm(const __half* __restrict__ A, const __half* __restrict__ B,
           const float* __restrict__ bias, void* __restrict__ Cv,
           int Ncols, int K)
{
    extern __shared__ __align__(16) char smem[];
    const uint32_t sb = smem_u32(smem);

    const int tid   = threadIdx.x;
    const int lane  = tid & 31;
    const int warp  = tid >> 5;      // 0..7
    const int warpM = warp >> 1;     // 0..3
    const int warpN = warp & 1;      // 0..1
    const int g     = lane >> 2;
    const int tig   = lane & 3;

    const __half* Aptr = A + (size_t)blockIdx.y * 128 * K;
    const __half* Bptr = B + (size_t)blockIdx.x * 128;

    float acc[2][8][4];
    #pragma unroll
    for (int i = 0; i < 2; i++)
        #pragma unroll
        for (int j = 0; j < 8; j++)
            #pragma unroll
            for (int l = 0; l < 4; l++) acc[i][j][l] = 0.f;

    auto issue = [&](int kt, int s) {
        const uint32_t aB = sb + s * STAGE_SZ;
        const uint32_t bB = aB + STAGE_A;
        #pragma unroll
        for (int it = 0; it < 4; it++) {
            int id = tid + it * 256;
            int r = id >> 3, c = id & 7;
            uint32_t dst = aB + r * 128 + ((c ^ (r & 7)) << 4);
            const __half* src = Aptr + (size_t)r * K + kt * BKH + c * 8;
            asm volatile("cp.async.cg.shared.global [%0], [%1], 16;" :: "r"(dst), "l"(src));
        }
        #pragma unroll
        for (int it = 0; it < 4; it++) {
            int id = tid + it * 256;
            int kr = id >> 4, c = id & 15;
            uint32_t dst = bB + kr * 256 + ((c ^ (kr & 7)) << 4);
            const __half* src = Bptr + (size_t)(kt * BKH + kr) * Ncols + c * 8;
            asm volatile("cp.async.cg.shared.global [%0], [%1], 16;" :: "r"(dst), "l"(src));
        }
    };

    auto compute = [&](int s) {
        const uint32_t a_base = sb + s * STAGE_SZ;
        const uint32_t b_base = a_base + STAGE_A;
        #pragma unroll
        for (int ks = 0; ks < 4; ks++) {
            uint32_t af[2][4], bf[8][2];
            #pragma unroll
            for (int mi = 0; mi < 2; mi++) {
                int r = warpM * 32 + mi * 16 + (lane & 15);
                int k = ks * 16 + ((lane >> 4) << 3);
                int c = k >> 3;
                uint32_t addr = a_base + r * 128 + ((c ^ (r & 7)) << 4);
                asm volatile(
                    "ldmatrix.sync.aligned.m8n8.x4.shared.b16 {%0,%1,%2,%3}, [%4];"
                    : "=r"(af[mi][0]), "=r"(af[mi][1]), "=r"(af[mi][2]), "=r"(af[mi][3])
                    : "r"(addr));
            }
            #pragma unroll
            for (int nip = 0; nip < 4; nip++) {
                int k = ks * 16 + (lane & 15);
                int n = warpN * 64 + nip * 16 + ((lane >> 4) << 3);
                int c = n >> 3;
                uint32_t addr = b_base + k * 256 + ((c ^ (k & 7)) << 4);
                asm volatile(
                    "ldmatrix.sync.aligned.m8n8.x4.trans.shared.b16 {%0,%1,%2,%3}, [%4];"
                    : "=r"(bf[2 * nip][0]), "=r"(bf[2 * nip][1]),
                      "=r"(bf[2 * nip + 1][0]), "=r"(bf[2 * nip + 1][1])
                    : "r"(addr));
            }
            #pragma unroll
            for (int mi = 0; mi < 2; mi++)
                #pragma unroll
                for (int ni = 0; ni < 8; ni++) {
                    asm volatile(
                        "mma.sync.aligned.m16n8k16.row.col.f32.f16.f16.f32 "
                        "{%0,%1,%2,%3}, {%4,%5,%6,%7}, {%8,%9}, {%0,%1,%2,%3};\n"
                        : "+f"(acc[mi][ni][0]), "+f"(acc[mi][ni][1]),
                          "+f"(acc[mi][ni][2]), "+f"(acc[mi][ni][3])
                        : "r"(af[mi][0]), "r"(af[mi][1]), "r"(af[mi][2]), "r"(af[mi][3]),
                          "r"(bf[ni][0]), "r"(bf[ni][1]));
                }
        }
    };

    const int nTiles = K / BKH;

    #pragma unroll
    for (int s = 0; s < NST - 1; s++) {
        issue(s, s);
        asm volatile("cp.async.commit_group;" ::: "memory");
    }

    for (int t = 0; t < nTiles; t++) {
        asm volatile("cp.async.wait_group %0;" :: "n"(NST - 2) : "memory");
        __syncthreads();
        const int nt = t + NST - 1;
        if (nt < nTiles) issue(nt, nt % NST);
        asm volatile("cp.async.commit_group;" ::: "memory");
        compute(t % NST);
    }

    // epilogue
    #pragma unroll
    for (int mi = 0; mi < 2; mi++) {
        #pragma unroll
        for (int ni = 0; ni < 8; ni++) {
            const int r0 = blockIdx.y * 128 + warpM * 32 + mi * 16 + g;
            const int c0 = blockIdx.x * 128 + warpN * 64 + ni * 8 + 2 * tig;
            #pragma unroll
            for (int hh = 0; hh < 2; hh++) {
                float v0 = acc[mi][ni][hh * 2 + 0];
                float v1 = acc[mi][ni][hh * 2 + 1];
                if (MODE == 1) {
                    // elu+1 on q,k columns, fp16 output
                    if (c0 < 2 * CH)     v0 = (v0 > 0.f) ? (v0 + 1.f) : expf(v0);
                    if (c0 + 1 < 2 * CH) v1 = (v1 > 0.f) ? (v1 + 1.f) : expf(v1);
                    __half2 p = __floats2half2_rn(v0, v1);
                    *(__half2*)((__half*)Cv + (size_t)(r0 + hh * 8) * Ncols + c0) = p;
                } else {
                    v0 += bias[c0]; v1 += bias[c0 + 1];
                    *(float2*)((float*)Cv + (size_t)(r0 + hh * 8) * Ncols + c0) =
                        make_float2(v0, v1);
                }
            }
        }
    }
}

// ================= prep: fp32 -> fp16 (rn) =================================
__global__ __launch_bounds__(256)
void cvt_f16_kernel(const float4* __restrict__ in, uint4* __restrict__ outp, int n8)
{
    int i = blockIdx.x * 256 + threadIdx.x;
    if (i < n8) {
        float4 a = in[2 * i], b = in[2 * i + 1];
        __half2 h0 = __floats2half2_rn(a.x, a.y);
        __half2 h1 = __floats2half2_rn(a.z, a.w);
        __half2 h2 = __floats2half2_rn(b.x, b.y);
        __half2 h3 = __floats2half2_rn(b.z, b.w);
        uint4 o;
        o.x = *reinterpret_cast<uint32_t*>(&h0);
        o.y = *reinterpret_cast<uint32_t*>(&h1);
        o.z = *reinterpret_cast<uint32_t*>(&h2);
        o.w = *reinterpret_cast<uint32_t*>(&h3);
        outp[i] = o;
    }
}

// ================= kv partial + reduce (fp16 in, fp32 accum) ===============
__global__ __launch_bounds__(256)
void kv_partial_kernel()
{
    const int bh    = blockIdx.x;
    const int chunk = blockIdx.y;
    const int b = bh / HEADS, h = bh % HEADS;

    __shared__ float ks[32][HD];
    __shared__ float vs[32][HD];

    const int tid = threadIdx.x;
    const int e0 = (tid % 16) * 4;
    const int d0 = (tid / 16) * 4;

    float acc[4][4] = {};
    float sacc[4] = {0.f, 0.f, 0.f, 0.f};

    const __half* base = g_qkvh + (size_t)b * SEQ * QKVC + h * HD;
    const int nBeg = chunk * (SEQ / KVCHUNKS);
    const int nEnd = nBeg + (SEQ / KVCHUNKS);

    const int lr = tid >> 3;          // 0..31 (row)
    const int lc = (tid & 7) * 8;     // 0..56 (col, 8 halves per thread)

    for (int n0 = nBeg; n0 < nEnd; n0 += 32) {
        {
            const __half* rowp = base + (size_t)(n0 + lr) * QKVC;
            uint4 kv4 = *(const uint4*)(rowp + CH + lc);
            uint4 vv4 = *(const uint4*)(rowp + 2 * CH + lc);
            const __half2* kp = (const __half2*)&kv4;
            const __half2* vp = (const __half2*)&vv4;
            #pragma unroll
            for (int j = 0; j < 4; j++) {
                float2 kf = __half22float2(kp[j]);
                float2 vf = __half22float2(vp[j]);
                ks[lr][lc + 2 * j]     = kf.x;
                ks[lr][lc + 2 * j + 1] = kf.y;
                vs[lr][lc + 2 * j]     = vf.x;
                vs[lr][lc + 2 * j + 1] = vf.y;
            }
        }
        __syncthreads();
        #pragma unroll 4
        for (int nn = 0; nn < 32; nn++) {
            float kr[4], vr[4];
            #pragma unroll
            for (int i = 0; i < 4; i++) kr[i] = ks[nn][d0 + i];
            #pragma unroll
            for (int j = 0; j < 4; j++) vr[j] = vs[nn][e0 + j];
            #pragma unroll
            for (int i = 0; i < 4; i++)
                #pragma unroll
                for (int j = 0; j < 4; j++)
                    acc[i][j] += kr[i] * vr[j];
            if (e0 == 0) {
                #pragma unroll
                for (int i = 0; i < 4; i++) sacc[i] += kr[i];
            }
        }
        __syncthreads();
    }

    float* kvp = g_kvp + ((size_t)chunk * BH + bh) * HD * HD;
    #pragma unroll
    for (int i = 0; i < 4; i++)
        *(float4*)&kvp[(d0 + i) * HD + e0] =
            make_float4(acc[i][0], acc[i][1], acc[i][2], acc[i][3]);
    if (e0 == 0) {
        #pragma unroll
        for (int i = 0; i < 4; i++)
            g_sumkp[((size_t)chunk * BH + bh) * HD + d0 + i] = sacc[i];
    }
}

__global__ __launch_bounds__(256)
void kv_reduce_kernel()
{
    const int bh = blockIdx.x;
    const int tid = threadIdx.x;
    for (int i = tid; i < HD * HD; i += 256) {
        float s = 0.f;
        #pragma unroll
        for (int c = 0; c < KVCHUNKS; c++)
            s += g_kvp[((size_t)c * BH + bh) * HD * HD + i];
        g_kvh[(size_t)bh * HD * HD + i] = __float2half_rn(s);
    }
    if (tid < HD) {
        float s = 0.f;
        #pragma unroll
        for (int c = 0; c < KVCHUNKS; c++)
            s += g_sumkp[((size_t)c * BH + bh) * HD + tid];
        g_sumk[(size_t)bh * HD + tid] = s;
    }
}

// ================= y via tensor cores: y = (q @ kv) / (q . sumk) ===========
__global__ __launch_bounds__(128)
void y_mma_kernel()
{
    __shared__ __align__(16) __half qs[128 * 64];
    __shared__ __align__(16) __half kvs[64 * 64];
    __shared__ float sumkS[HD];
    __shared__ float denomS[128];

    const int tid  = threadIdx.x;
    const int lane = tid & 31;
    const int warp = tid >> 5;
    const int bh   = blockIdx.y;
    const int b    = bh / HEADS, h = bh % HEADS;
    const int n0   = blockIdx.x * 128;

    const __half* qg = g_qkvh + ((size_t)b * SEQ + n0) * QKVC + h * HD;

    // q: straight fp16 copy into swizzled smem (1024 chunks of 16B)
    #pragma unroll
    for (int it = 0; it < 8; it++) {
        int id = tid + it * 128;
        int r = id >> 3, c = id & 7;
        uint4 o = *(const uint4*)(qg + (size_t)r * QKVC + c * 8);
        *(uint4*)((char*)qs + r * 128 + (((c ^ (r & 7))) << 4)) = o;
    }
    const __half* kvg = g_kvh + (size_t)bh * HD * HD;
    #pragma unroll
    for (int it = 0; it < 4; it++) {
        int id = tid + it * 128;
        int d = id >> 3, c = id & 7;
        uint4 o = *(const uint4*)(kvg + d * HD + c * 8);
        *(uint4*)((char*)kvs + d * 128 + (((c ^ (d & 7))) << 4)) = o;
    }
    if (tid < HD) sumkS[tid] = g_sumk[(size_t)bh * HD + tid];
    __syncthreads();

    // denominator: fp16 q row dotted with fp32 sumk
    {
        const __half* qr = qg + (size_t)tid * QKVC;
        float s = 0.f;
        #pragma unroll
        for (int d = 0; d < HD; d += 8) {
            uint4 v = *(const uint4*)(qr + d);
            const __half2* hp = (const __half2*)&v;
            #pragma unroll
            for (int j = 0; j < 4; j++) {
                float2 f = __half22float2(hp[j]);
                s += f.x * sumkS[d + 2 * j] + f.y * sumkS[d + 2 * j + 1];
            }
        }
        denomS[tid] = 1.0f / s;
    }

    const uint32_t qb = smem_u32(qs);
    const uint32_t kb = smem_u32(kvs);

    float acc[2][8][4];
    #pragma unroll
    for (int i = 0; i < 2; i++)
        #pragma unroll
        for (int j = 0; j < 8; j++)
            #pragma unroll
            for (int l = 0; l < 4; l++) acc[i][j][l] = 0.f;

    #pragma unroll
    for (int ks = 0; ks < 4; ks++) {
        uint32_t af[2][4], bf[8][2];
        #pragma unroll
        for (int mi = 0; mi < 2; mi++) {
            int r = warp * 32 + mi * 16 + (lane & 15);
            int k = ks * 16 + ((lane >> 4) << 3);
            int c = k >> 3;
            uint32_t addr = qb + r * 128 + (((c ^ (r & 7))) << 4);
            asm volatile(
                "ldmatrix.sync.aligned.m8n8.x4.shared.b16 {%0,%1,%2,%3}, [%4];"
                : "=r"(af[mi][0]), "=r"(af[mi][1]), "=r"(af[mi][2]), "=r"(af[mi][3])
                : "r"(addr));
        }
        #pragma unroll
        for (int nip = 0; nip < 4; nip++) {
            int k = ks * 16 + (lane & 15);
            int n = nip * 16 + ((lane >> 4) << 3);
            int c = n >> 3;
            uint32_t addr = kb + k * 128 + (((c ^ (k & 7))) << 4);
            asm volatile(
                "ldmatrix.sync.aligned.m8n8.x4.trans.shared.b16 {%0,%1,%2,%3}, [%4];"
                : "=r"(bf[2 * nip][0]), "=r"(bf[2 * nip][1]),
                  "=r"(bf[2 * nip + 1][0]), "=r"(bf[2 * nip + 1][1])
                : "r"(addr));
        }
        #pragma unroll
        for (int mi = 0; mi < 2; mi++)
            #pragma unroll
            for (int ni = 0; ni < 8; ni++) {
                asm volatile(
                    "mma.sync.aligned.m16n8k16.row.col.f32.f16.f16.f32 "
                    "{%0,%1,%2,%3}, {%4,%5,%6,%7}, {%8,%9}, {%0,%1,%2,%3};\n"
                    : "+f"(acc[mi][ni][0]), "+f"(acc[mi][ni][1]),
                      "+f"(acc[mi][ni][2]), "+f"(acc[mi][ni][3])
                    : "r"(af[mi][0]), "r"(af[mi][1]), "r"(af[mi][2]), "r"(af[mi][3]),
                      "r"(bf[ni][0]), "r"(bf[ni][1]));
            }
    }

    __syncwarp();

    const int g = lane >> 2, tig = lane & 3;
    #pragma unroll
    for (int mi = 0; mi < 2; mi++) {
        #pragma unroll
        for (int hh = 0; hh < 2; hh++) {
            const int rl = warp * 32 + mi * 16 + g + hh * 8;
            const float inv = denomS[rl];
            __half* yrow = g_yh + ((size_t)b * SEQ + n0 + rl) * CH + h * HD;
            #pragma unroll
            for (int ni = 0; ni < 8; ni++) {
                const int col = ni * 8 + 2 * tig;
                __half2 p = __floats2half2_rn(acc[mi][ni][hh * 2 + 0] * inv,
                                              acc[mi][ni][hh * 2 + 1] * inv);
                *(__half2*)(yrow + col) = p;
            }
        }
    }
}

// ---------------------------------------------------------------------------
extern "C" void kernel_launch(void* const* d_in, const int* in_sizes, int n_in,
                              void* d_out, int out_size)
{
    const float* x      = (const float*)d_in[0];
    const float* w_qkv  = (const float*)d_in[1];
    const float* w_proj = (const float*)d_in[2];
    const float* b_proj = (const float*)d_in[3];
    float* out = (float*)d_out;

    __half *qkvh_p, *xh_p, *wqkvh_p, *wprojh_p, *yh_p;
    cudaGetSymbolAddress((void**)&qkvh_p,   g_qkvh);
    cudaGetSymbolAddress((void**)&xh_p,     g_xh);
    cudaGetSymbolAddress((void**)&wqkvh_p,  g_wqkvh);
    cudaGetSymbolAddress((void**)&wprojh_p, g_wprojh);
    cudaGetSymbolAddress((void**)&yh_p,     g_yh);

    cudaFuncSetAttribute(hgemm<1>, cudaFuncAttributeMaxDynamicSharedMemorySize, HG_SMEM);
    cudaFuncSetAttribute(hgemm<2>, cudaFuncAttributeMaxDynamicSharedMemorySize, HG_SMEM);

    // 0) convert inputs to fp16 (rn)
    cvt_f16_kernel<<<(ROWS * CH / 8 + 255) / 256, 256>>>(
        (const float4*)x, (uint4*)xh_p, ROWS * CH / 8);
    cvt_f16_kernel<<<(CH * QKVC / 8 + 255) / 256, 256>>>(
        (const float4*)w_qkv, (uint4*)wqkvh_p, CH * QKVC / 8);
    cvt_f16_kernel<<<(CH * CH / 8 + 255) / 256, 256>>>(
        (const float4*)w_proj, (uint4*)wprojh_p, CH * CH / 8);

    // 1) qkv = x @ w_qkv (fp16 TC), elu+1 fused, fp16 output
    {
        dim3 grid(QKVC / 128, ROWS / 128);
        hgemm<1><<<grid, 256, HG_SMEM>>>(xh_p, wqkvh_p, nullptr, qkvh_p, QKVC, CH);
    }
    // 2) kv outer product (seq-split, fp16 in / fp32 accum) + reduce
    {
        dim3 grid(BH, KVCHUNKS);
        kv_partial_kernel<<<grid, 256>>>();
        kv_reduce_kernel<<<BH, 256>>>();
    }
    // 3) y = (q @ kv) / (q . sumk) on tensor cores, fp16 out
    {
        dim3 grid(SEQ / 128, BH);
        y_mma_kernel<<<grid, 128>>>();
    }
    // 4) out = y @ w_proj + b_proj (fp16 TC, fp32 out)
    {
        dim3 grid(CH / 128, ROWS / 128);
        hgemm<2><<<grid, 256, HG_SMEM>>>(yh_p, wprojh_p, b_proj, out, CH, CH);
    }
}

// round 11
// speedup vs baseline: 6.5771x; 1.0524x over previous
#include <cuda_runtime.h>
#include <cuda_fp16.h>
#include <math.h>
#include <stdint.h>

// Problem constants: B=4, N=4096, C=1024, H=16, D=64
#define BATCH 4
#define SEQ   4096
#define CH    1024
#define HEADS 16
#define HD    64
#define ROWS  (BATCH*SEQ)        // 16384
#define QKVC  (3*CH)             // 3072
#define BH    (BATCH*HEADS)      // 64
#define KVCHUNKS 8

// ---------------- scratch (device globals: allocation-free) ----------------
__device__ __align__(256) __half g_qkvh  [(size_t)ROWS * QKVC];  // qkv fp16 (elu+1 on q,k)
__device__ __align__(256) __half g_xh    [(size_t)ROWS * CH];
__device__ __align__(256) __half g_wqkvh [(size_t)CH * QKVC];
__device__ __align__(256) __half g_wprojh[(size_t)CH * CH];
__device__ __align__(256) __half g_yh    [(size_t)ROWS * CH];
__device__ __align__(256) __half g_kvh   [(size_t)BH * HD * HD];
__device__ float g_sumk [(size_t)BH * HD];
__device__ float g_kvp  [(size_t)KVCHUNKS * BH * HD * HD];
__device__ float g_sumkp[(size_t)KVCHUNKS * BH * HD];

__device__ __forceinline__ uint32_t smem_u32(const void* p) {
    uint32_t a;
    asm("{ .reg .u64 t; cvta.to.shared.u64 t, %1; cvt.u32.u64 %0, t; }" : "=r"(a) : "l"(p));
    return a;
}

// ===== fp16 GEMM: 128 threads = 4 warps (2x2), warp tile 64x64, =====
// ===== cp.async 3-stage, 2 CTAs/SM.  Block 128x128, BK=64.        =====
// MODE 1: elu+1 on cols < 2048, output fp16. MODE 2: +bias, output fp32.
#define BKH 64
#define NST 3
#define STAGE_A (128 * BKH * 2)            // 16384 B
#define STAGE_B (BKH * 128 * 2)            // 16384 B
#define STAGE_SZ (STAGE_A + STAGE_B)       // 32768 B
#define HG_SMEM (NST * STAGE_SZ)           // 98304 B

template <int MODE>
__global__ __launch_bounds__(128, 2)
void hgemm(const __half* __restrict__ A, const __half* __restrict__ B,
           const float* __restrict__ bias, void* __restrict__ Cv,
           int Ncols, int K)
{
    extern __shared__ __align__(16) char smem[];
    const uint32_t sb = smem_u32(smem);

    const int tid   = threadIdx.x;
    const int lane  = tid & 31;
    const int warp  = tid >> 5;      // 0..3
    const int warpM = warp >> 1;     // 0..1  (64-row strips)
    const int warpN = warp & 1;      // 0..1  (64-col strips)
    const int g     = lane >> 2;
    const int tig   = lane & 3;

    const __half* Aptr = A + (size_t)blockIdx.y * 128 * K;
    const __half* Bptr = B + (size_t)blockIdx.x * 128;

    float acc[4][8][4];
    #pragma unroll
    for (int i = 0; i < 4; i++)
        #pragma unroll
        for (int j = 0; j < 8; j++)
            #pragma unroll
            for (int l = 0; l < 4; l++) acc[i][j][l] = 0.f;

    auto issue = [&](int kt, int s) {
        const uint32_t aB = sb + s * STAGE_SZ;
        const uint32_t bB = aB + STAGE_A;
        // A: 128 rows x 8 chunks = 1024 chunks, 8/thread
        #pragma unroll
        for (int it = 0; it < 8; it++) {
            int id = tid + it * 128;
            int r = id >> 3, c = id & 7;
            uint32_t dst = aB + r * 128 + ((c ^ (r & 7)) << 4);
            const __half* src = Aptr + (size_t)r * K + kt * BKH + c * 8;
            asm volatile("cp.async.cg.shared.global [%0], [%1], 16;" :: "r"(dst), "l"(src));
        }
        // B: 64 rows x 16 chunks = 1024 chunks, 8/thread
        #pragma unroll
        for (int it = 0; it < 8; it++) {
            int id = tid + it * 128;
            int kr = id >> 4, c = id & 15;
            uint32_t dst = bB + kr * 256 + ((c ^ (kr & 7)) << 4);
            const __half* src = Bptr + (size_t)(kt * BKH + kr) * Ncols + c * 8;
            asm volatile("cp.async.cg.shared.global [%0], [%1], 16;" :: "r"(dst), "l"(src));
        }
    };

    auto compute = [&](int s) {
        const uint32_t a_base = sb + s * STAGE_SZ;
        const uint32_t b_base = a_base + STAGE_A;
        #pragma unroll
        for (int ks = 0; ks < 4; ks++) {
            uint32_t af[4][4], bf[8][2];
            #pragma unroll
            for (int mi = 0; mi < 4; mi++) {
                int r = warpM * 64 + mi * 16 + (lane & 15);
                int k = ks * 16 + ((lane >> 4) << 3);
                int c = k >> 3;
                uint32_t addr = a_base + r * 128 + ((c ^ (r & 7)) << 4);
                asm volatile(
                    "ldmatrix.sync.aligned.m8n8.x4.shared.b16 {%0,%1,%2,%3}, [%4];"
                    : "=r"(af[mi][0]), "=r"(af[mi][1]), "=r"(af[mi][2]), "=r"(af[mi][3])
                    : "r"(addr));
            }
            #pragma unroll
            for (int nip = 0; nip < 4; nip++) {
                int k = ks * 16 + (lane & 15);
                int n = warpN * 64 + nip * 16 + ((lane >> 4) << 3);
                int c = n >> 3;
                uint32_t addr = b_base + k * 256 + ((c ^ (k & 7)) << 4);
                asm volatile(
                    "ldmatrix.sync.aligned.m8n8.x4.trans.shared.b16 {%0,%1,%2,%3}, [%4];"
                    : "=r"(bf[2 * nip][0]), "=r"(bf[2 * nip][1]),
                      "=r"(bf[2 * nip + 1][0]), "=r"(bf[2 * nip + 1][1])
                    : "r"(addr));
            }
            #pragma unroll
            for (int mi = 0; mi < 4; mi++)
                #pragma unroll
                for (int ni = 0; ni < 8; ni++) {
                    asm volatile(
                        "mma.sync.aligned.m16n8k16.row.col.f32.f16.f16.f32 "
                        "{%0,%1,%2,%3}, {%4,%5,%6,%7}, {%8,%9}, {%0,%1,%2,%3};\n"
                        : "+f"(acc[mi][ni][0]), "+f"(acc[mi][ni][1]),
                          "+f"(acc[mi][ni][2]), "+f"(acc[mi][ni][3])
                        : "r"(af[mi][0]), "r"(af[mi][1]), "r"(af[mi][2]), "r"(af[mi][3]),
                          "r"(bf[ni][0]), "r"(bf[ni][1]));
                }
        }
    };

    const int nTiles = K / BKH;

    #pragma unroll
    for (int s = 0; s < NST - 1; s++) {
        issue(s, s);
        asm volatile("cp.async.commit_group;" ::: "memory");
    }

    for (int t = 0; t < nTiles; t++) {
        asm volatile("cp.async.wait_group %0;" :: "n"(NST - 2) : "memory");
        __syncthreads();
        const int nt = t + NST - 1;
        if (nt < nTiles) issue(nt, nt % NST);
        asm volatile("cp.async.commit_group;" ::: "memory");
        compute(t % NST);
    }

    // epilogue
    #pragma unroll
    for (int mi = 0; mi < 4; mi++) {
        #pragma unroll
        for (int ni = 0; ni < 8; ni++) {
            const int r0 = blockIdx.y * 128 + warpM * 64 + mi * 16 + g;
            const int c0 = blockIdx.x * 128 + warpN * 64 + ni * 8 + 2 * tig;
            #pragma unroll
            for (int hh = 0; hh < 2; hh++) {
                float v0 = acc[mi][ni][hh * 2 + 0];
                float v1 = acc[mi][ni][hh * 2 + 1];
                if (MODE == 1) {
                    if (c0 < 2 * CH)     v0 = (v0 > 0.f) ? (v0 + 1.f) : expf(v0);
                    if (c0 + 1 < 2 * CH) v1 = (v1 > 0.f) ? (v1 + 1.f) : expf(v1);
                    __half2 p = __floats2half2_rn(v0, v1);
                    *(__half2*)((__half*)Cv + (size_t)(r0 + hh * 8) * Ncols + c0) = p;
                } else {
                    v0 += bias[c0]; v1 += bias[c0 + 1];
                    *(float2*)((float*)Cv + (size_t)(r0 + hh * 8) * Ncols + c0) =
                        make_float2(v0, v1);
                }
            }
        }
    }
}

// ================= prep: fp32 -> fp16 (rn) =================================
__global__ __launch_bounds__(256)
void cvt_f16_kernel(const float4* __restrict__ in, uint4* __restrict__ outp, int n8)
{
    int i = blockIdx.x * 256 + threadIdx.x;
    if (i < n8) {
        float4 a = in[2 * i], b = in[2 * i + 1];
        __half2 h0 = __floats2half2_rn(a.x, a.y);
        __half2 h1 = __floats2half2_rn(a.z, a.w);
        __half2 h2 = __floats2half2_rn(b.x, b.y);
        __half2 h3 = __floats2half2_rn(b.z, b.w);
        uint4 o;
        o.x = *reinterpret_cast<uint32_t*>(&h0);
        o.y = *reinterpret_cast<uint32_t*>(&h1);
        o.z = *reinterpret_cast<uint32_t*>(&h2);
        o.w = *reinterpret_cast<uint32_t*>(&h3);
        outp[i] = o;
    }
}

// ================= kv partial + reduce (fp16 in, fp32 accum) ===============
__global__ __launch_bounds__(256)
void kv_partial_kernel()
{
    const int bh    = blockIdx.x;
    const int chunk = blockIdx.y;
    const int b = bh / HEADS, h = bh % HEADS;

    __shared__ float ks[32][HD];
    __shared__ float vs[32][HD];

    const int tid = threadIdx.x;
    const int e0 = (tid % 16) * 4;
    const int d0 = (tid / 16) * 4;

    float acc[4][4] = {};
    float sacc[4] = {0.f, 0.f, 0.f, 0.f};

    const __half* base = g_qkvh + (size_t)b * SEQ * QKVC + h * HD;
    const int nBeg = chunk * (SEQ / KVCHUNKS);
    const int nEnd = nBeg + (SEQ / KVCHUNKS);

    const int lr = tid >> 3;
    const int lc = (tid & 7) * 8;

    for (int n0 = nBeg; n0 < nEnd; n0 += 32) {
        {
            const __half* rowp = base + (size_t)(n0 + lr) * QKVC;
            uint4 kv4 = *(const uint4*)(rowp + CH + lc);
            uint4 vv4 = *(const uint4*)(rowp + 2 * CH + lc);
            const __half2* kp = (const __half2*)&kv4;
            const __half2* vp = (const __half2*)&vv4;
            #pragma unroll
            for (int j = 0; j < 4; j++) {
                float2 kf = __half22float2(kp[j]);
                float2 vf = __half22float2(vp[j]);
                ks[lr][lc + 2 * j]     = kf.x;
                ks[lr][lc + 2 * j + 1] = kf.y;
                vs[lr][lc + 2 * j]     = vf.x;
                vs[lr][lc + 2 * j + 1] = vf.y;
            }
        }
        __syncthreads();
        #pragma unroll 4
        for (int nn = 0; nn < 32; nn++) {
            float kr[4], vr[4];
            #pragma unroll
            for (int i = 0; i < 4; i++) kr[i] = ks[nn][d0 + i];
            #pragma unroll
            for (int j = 0; j < 4; j++) vr[j] = vs[nn][e0 + j];
            #pragma unroll
            for (int i = 0; i < 4; i++)
                #pragma unroll
                for (int j = 0; j < 4; j++)
                    acc[i][j] += kr[i] * vr[j];
            if (e0 == 0) {
                #pragma unroll
                for (int i = 0; i < 4; i++) sacc[i] += kr[i];
            }
        }
        __syncthreads();
    }

    float* kvp = g_kvp + ((size_t)chunk * BH + bh) * HD * HD;
    #pragma unroll
    for (int i = 0; i < 4; i++)
        *(float4*)&kvp[(d0 + i) * HD + e0] =
            make_float4(acc[i][0], acc[i][1], acc[i][2], acc[i][3]);
    if (e0 == 0) {
        #pragma unroll
        for (int i = 0; i < 4; i++)
            g_sumkp[((size_t)chunk * BH + bh) * HD + d0 + i] = sacc[i];
    }
}

__global__ __launch_bounds__(256)
void kv_reduce_kernel()
{
    const int bh = blockIdx.x;
    const int tid = threadIdx.x;
    for (int i = tid; i < HD * HD; i += 256) {
        float s = 0.f;
        #pragma unroll
        for (int c = 0; c < KVCHUNKS; c++)
            s += g_kvp[((size_t)c * BH + bh) * HD * HD + i];
        g_kvh[(size_t)bh * HD * HD + i] = __float2half_rn(s);
    }
    if (tid < HD) {
        float s = 0.f;
        #pragma unroll
        for (int c = 0; c < KVCHUNKS; c++)
            s += g_sumkp[((size_t)c * BH + bh) * HD + tid];
        g_sumk[(size_t)bh * HD + tid] = s;
    }
}

// ================= y via tensor cores: y = (q @ kv) / (q . sumk) ===========
__global__ __launch_bounds__(128)
void y_mma_kernel()
{
    __shared__ __align__(16) __half qs[128 * 64];
    __shared__ __align__(16) __half kvs[64 * 64];
    __shared__ float sumkS[HD];
    __shared__ float denomS[128];

    const int tid  = threadIdx.x;
    const int lane = tid & 31;
    const int warp = tid >> 5;
    const int bh   = blockIdx.y;
    const int b    = bh / HEADS, h = bh % HEADS;
    const int n0   = blockIdx.x * 128;

    const __half* qg = g_qkvh + ((size_t)b * SEQ + n0) * QKVC + h * HD;

    #pragma unroll
    for (int it = 0; it < 8; it++) {
        int id = tid + it * 128;
        int r = id >> 3, c = id & 7;
        uint4 o = *(const uint4*)(qg + (size_t)r * QKVC + c * 8);
        *(uint4*)((char*)qs + r * 128 + (((c ^ (r & 7))) << 4)) = o;
    }
    const __half* kvg = g_kvh + (size_t)bh * HD * HD;
    #pragma unroll
    for (int it = 0; it < 4; it++) {
        int id = tid + it * 128;
        int d = id >> 3, c = id & 7;
        uint4 o = *(const uint4*)(kvg + d * HD + c * 8);
        *(uint4*)((char*)kvs + d * 128 + (((c ^ (d & 7))) << 4)) = o;
    }
    if (tid < HD) sumkS[tid] = g_sumk[(size_t)bh * HD + tid];
    __syncthreads();

    {
        const __half* qr = qg + (size_t)tid * QKVC;
        float s = 0.f;
        #pragma unroll
        for (int d = 0; d < HD; d += 8) {
            uint4 v = *(const uint4*)(qr + d);
            const __half2* hp = (const __half2*)&v;
            #pragma unroll
            for (int j = 0; j < 4; j++) {
                float2 f = __half22float2(hp[j]);
                s += f.x * sumkS[d + 2 * j] + f.y * sumkS[d + 2 * j + 1];
            }
        }
        denomS[tid] = 1.0f / s;
    }

    const uint32_t qb = smem_u32(qs);
    const uint32_t kb = smem_u32(kvs);

    float acc[2][8][4];
    #pragma unroll
    for (int i = 0; i < 2; i++)
        #pragma unroll
        for (int j = 0; j < 8; j++)
            #pragma unroll
            for (int l = 0; l < 4; l++) acc[i][j][l] = 0.f;

    #pragma unroll
    for (int ks = 0; ks < 4; ks++) {
        uint32_t af[2][4], bf[8][2];
        #pragma unroll
        for (int mi = 0; mi < 2; mi++) {
            int r = warp * 32 + mi * 16 + (lane & 15);
            int k = ks * 16 + ((lane >> 4) << 3);
            int c = k >> 3;
            uint32_t addr = qb + r * 128 + (((c ^ (r & 7))) << 4);
            asm volatile(
                "ldmatrix.sync.aligned.m8n8.x4.shared.b16 {%0,%1,%2,%3}, [%4];"
                : "=r"(af[mi][0]), "=r"(af[mi][1]), "=r"(af[mi][2]), "=r"(af[mi][3])
                : "r"(addr));
        }
        #pragma unroll
        for (int nip = 0; nip < 4; nip++) {
            int k = ks * 16 + (lane & 15);
            int n = nip * 16 + ((lane >> 4) << 3);
            int c = n >> 3;
            uint32_t addr = kb + k * 128 + (((c ^ (k & 7))) << 4);
            asm volatile(
                "ldmatrix.sync.aligned.m8n8.x4.trans.shared.b16 {%0,%1,%2,%3}, [%4];"
                : "=r"(bf[2 * nip][0]), "=r"(bf[2 * nip][1]),
                  "=r"(bf[2 * nip + 1][0]), "=r"(bf[2 * nip + 1][1])
                : "r"(addr));
        }
        #pragma unroll
        for (int mi = 0; mi < 2; mi++)
            #pragma unroll
            for (int ni = 0; ni < 8; ni++) {
                asm volatile(
                    "mma.sync.aligned.m16n8k16.row.col.f32.f16.f16.f32 "
                    "{%0,%1,%2,%3}, {%4,%5,%6,%7}, {%8,%9}, {%0,%1,%2,%3};\n"
                    : "+f"(acc[mi][ni][0]), "+f"(acc[mi][ni][1]),
                      "+f"(acc[mi][ni][2]), "+f"(acc[mi][ni][3])
                    : "r"(af[mi][0]), "r"(af[mi][1]), "r"(af[mi][2]), "r"(af[mi][3]),
                      "r"(bf[ni][0]), "r"(bf[ni][1]));
            }
    }

    __syncwarp();

    const int g = lane >> 2, tig = lane & 3;
    #pragma unroll
    for (int mi = 0; mi < 2; mi++) {
        #pragma unroll
        for (int hh = 0; hh < 2; hh++) {
            const int rl = warp * 32 + mi * 16 + g + hh * 8;
            const float inv = denomS[rl];
            __half* yrow = g_yh + ((size_t)b * SEQ + n0 + rl) * CH + h * HD;
            #pragma unroll
            for (int ni = 0; ni < 8; ni++) {
                const int col = ni * 8 + 2 * tig;
                __half2 p = __floats2half2_rn(acc[mi][ni][hh * 2 + 0] * inv,
                                              acc[mi][ni][hh * 2 + 1] * inv);
                *(__half2*)(yrow + col) = p;
            }
        }
    }
}

// ---------------------------------------------------------------------------
extern "C" void kernel_launch(void* const* d_in, const int* in_sizes, int n_in,
                              void* d_out, int out_size)
{
    const float* x      = (const float*)d_in[0];
    const float* w_qkv  = (const float*)d_in[1];
    const float* w_proj = (const float*)d_in[2];
    const float* b_proj = (const float*)d_in[3];
    float* out = (float*)d_out;

    __half *qkvh_p, *xh_p, *wqkvh_p, *wprojh_p, *yh_p;
    cudaGetSymbolAddress((void**)&qkvh_p,   g_qkvh);
    cudaGetSymbolAddress((void**)&xh_p,     g_xh);
    cudaGetSymbolAddress((void**)&wqkvh_p,  g_wqkvh);
    cudaGetSymbolAddress((void**)&wprojh_p, g_wprojh);
    cudaGetSymbolAddress((void**)&yh_p,     g_yh);

    cudaFuncSetAttribute(hgemm<1>, cudaFuncAttributeMaxDynamicSharedMemorySize, HG_SMEM);
    cudaFuncSetAttribute(hgemm<2>, cudaFuncAttributeMaxDynamicSharedMemorySize, HG_SMEM);

    // 0) convert inputs to fp16 (rn)
    cvt_f16_kernel<<<(ROWS * CH / 8 + 255) / 256, 256>>>(
        (const float4*)x, (uint4*)xh_p, ROWS * CH / 8);
    cvt_f16_kernel<<<(CH * QKVC / 8 + 255) / 256, 256>>>(
        (const float4*)w_qkv, (uint4*)wqkvh_p, CH * QKVC / 8);
    cvt_f16_kernel<<<(CH * CH / 8 + 255) / 256, 256>>>(
        (const float4*)w_proj, (uint4*)wprojh_p, CH * CH / 8);

    // 1) qkv = x @ w_qkv (fp16 TC, 64x64 warp tiles), elu+1 fused, fp16 out
    {
        dim3 grid(QKVC / 128, ROWS / 128);
        hgemm<1><<<grid, 128, HG_SMEM>>>(xh_p, wqkvh_p, nullptr, qkvh_p, QKVC, CH);
    }
    // 2) kv outer product (seq-split, fp16 in / fp32 accum) + reduce
    {
        dim3 grid(BH, KVCHUNKS);
        kv_partial_kernel<<<grid, 256>>>();
        kv_reduce_kernel<<<BH, 256>>>();
    }
    // 3) y = (q @ kv) / (q . sumk) on tensor cores, fp16 out
    {
        dim3 grid(SEQ / 128, BH);
        y_mma_kernel<<<grid, 128>>>();
    }
    // 4) out = y @ w_proj + b_proj (fp16 TC, fp32 out)
    {
        dim3 grid(CH / 128, ROWS / 128);
        hgemm<2><<<grid, 128, HG_SMEM>>>(yh_p, wprojh_p, b_proj, out, CH, CH);
    }
}

// round 12
// speedup vs baseline: 7.3979x; 1.1248x over previous
#include <cuda_runtime.h>
#include <cuda_fp16.h>
#include <math.h>
#include <stdint.h>

// Problem constants: B=4, N=4096, C=1024, H=16, D=64
#define BATCH 4
#define SEQ   4096
#define CH    1024
#define HEADS 16
#define HD    64
#define ROWS  (BATCH*SEQ)        // 16384
#define QKVC  (3*CH)             // 3072
#define BH    (BATCH*HEADS)      // 64
#define KVCHUNKS 8

// ---------------- scratch (device globals: allocation-free) ----------------
__device__ __align__(256) __half g_qkvh  [(size_t)ROWS * QKVC];  // qkv fp16 (elu+1 on q,k)
__device__ __align__(256) __half g_xh    [(size_t)ROWS * CH];
__device__ __align__(256) __half g_wqkvh [(size_t)CH * QKVC];
__device__ __align__(256) __half g_wprojh[(size_t)CH * CH];
__device__ __align__(256) __half g_yh    [(size_t)ROWS * CH];
__device__ __align__(256) __half g_kvh   [(size_t)BH * HD * HD];
__device__ float g_sumk [(size_t)BH * HD];
__device__ float g_kvp  [(size_t)KVCHUNKS * BH * HD * HD];
__device__ float g_sumkp[(size_t)KVCHUNKS * BH * HD];

__device__ __forceinline__ uint32_t smem_u32(const void* p) {
    uint32_t a;
    asm("{ .reg .u64 t; cvta.to.shared.u64 t, %1; cvt.u32.u64 %0, t; }" : "=r"(a) : "l"(p));
    return a;
}

#define MMA16816(acc, af, b0, b1)                                              \
    asm("mma.sync.aligned.m16n8k16.row.col.f32.f16.f16.f32 "                   \
        "{%0,%1,%2,%3}, {%4,%5,%6,%7}, {%8,%9}, {%0,%1,%2,%3};\n"              \
        : "+f"((acc)[0]), "+f"((acc)[1]), "+f"((acc)[2]), "+f"((acc)[3])       \
        : "r"((af)[0]), "r"((af)[1]), "r"((af)[2]), "r"((af)[3]),              \
          "r"(b0), "r"(b1))

// ===== fp16 GEMM: 128 threads = 4 warps (2x2), warp tile 64x64, =====
// ===== cp.async 3-stage, 2 CTAs/SM.  Block 128x128, BK=64.        =====
#define BKH 64
#define NST 3
#define STAGE_A (128 * BKH * 2)
#define STAGE_B (BKH * 128 * 2)
#define STAGE_SZ (STAGE_A + STAGE_B)
#define HG_SMEM (NST * STAGE_SZ)           // 98304 B

template <int MODE>
__global__ __launch_bounds__(128, 2)
void hgemm(const __half* __restrict__ A, const __half* __restrict__ B,
           const float* __restrict__ bias, void* __restrict__ Cv,
           int Ncols, int K)
{
    extern __shared__ __align__(16) char smem[];
    const uint32_t sb = smem_u32(smem);

    const int tid   = threadIdx.x;
    const int lane  = tid & 31;
    const int warp  = tid >> 5;
    const int warpM = warp >> 1;
    const int warpN = warp & 1;
    const int g     = lane >> 2;
    const int tig   = lane & 3;

    const __half* Aptr = A + (size_t)blockIdx.y * 128 * K;
    const __half* Bptr = B + (size_t)blockIdx.x * 128;

    float acc[4][8][4];
    #pragma unroll
    for (int i = 0; i < 4; i++)
        #pragma unroll
        for (int j = 0; j < 8; j++)
            #pragma unroll
            for (int l = 0; l < 4; l++) acc[i][j][l] = 0.f;

    auto issue = [&](int kt, int s) {
        const uint32_t aB = sb + s * STAGE_SZ;
        const uint32_t bB = aB + STAGE_A;
        #pragma unroll
        for (int it = 0; it < 8; it++) {
            int id = tid + it * 128;
            int r = id >> 3, c = id & 7;
            uint32_t dst = aB + r * 128 + ((c ^ (r & 7)) << 4);
            const __half* src = Aptr + (size_t)r * K + kt * BKH + c * 8;
            asm volatile("cp.async.cg.shared.global [%0], [%1], 16;" :: "r"(dst), "l"(src));
        }
        #pragma unroll
        for (int it = 0; it < 8; it++) {
            int id = tid + it * 128;
            int kr = id >> 4, c = id & 15;
            uint32_t dst = bB + kr * 256 + ((c ^ (kr & 7)) << 4);
            const __half* src = Bptr + (size_t)(kt * BKH + kr) * Ncols + c * 8;
            asm volatile("cp.async.cg.shared.global [%0], [%1], 16;" :: "r"(dst), "l"(src));
        }
    };

    auto compute = [&](int s) {
        const uint32_t a_base = sb + s * STAGE_SZ;
        const uint32_t b_base = a_base + STAGE_A;
        #pragma unroll
        for (int ks = 0; ks < 4; ks++) {
            uint32_t af[4][4], bf[8][2];
            #pragma unroll
            for (int mi = 0; mi < 4; mi++) {
                int r = warpM * 64 + mi * 16 + (lane & 15);
                int k = ks * 16 + ((lane >> 4) << 3);
                int c = k >> 3;
                uint32_t addr = a_base + r * 128 + ((c ^ (r & 7)) << 4);
                asm volatile(
                    "ldmatrix.sync.aligned.m8n8.x4.shared.b16 {%0,%1,%2,%3}, [%4];"
                    : "=r"(af[mi][0]), "=r"(af[mi][1]), "=r"(af[mi][2]), "=r"(af[mi][3])
                    : "r"(addr));
            }
            #pragma unroll
            for (int nip = 0; nip < 4; nip++) {
                int k = ks * 16 + (lane & 15);
                int n = warpN * 64 + nip * 16 + ((lane >> 4) << 3);
                int c = n >> 3;
                uint32_t addr = b_base + k * 256 + ((c ^ (k & 7)) << 4);
                asm volatile(
                    "ldmatrix.sync.aligned.m8n8.x4.trans.shared.b16 {%0,%1,%2,%3}, [%4];"
                    : "=r"(bf[2 * nip][0]), "=r"(bf[2 * nip][1]),
                      "=r"(bf[2 * nip + 1][0]), "=r"(bf[2 * nip + 1][1])
                    : "r"(addr));
            }
            #pragma unroll
            for (int mi = 0; mi < 4; mi++)
                #pragma unroll
                for (int ni = 0; ni < 8; ni++)
                    MMA16816(acc[mi][ni], af[mi], bf[ni][0], bf[ni][1]);
        }
    };

    const int nTiles = K / BKH;

    #pragma unroll
    for (int s = 0; s < NST - 1; s++) {
        issue(s, s);
        asm volatile("cp.async.commit_group;" ::: "memory");
    }

    for (int t = 0; t < nTiles; t++) {
        asm volatile("cp.async.wait_group %0;" :: "n"(NST - 2) : "memory");
        __syncthreads();
        const int nt = t + NST - 1;
        if (nt < nTiles) issue(nt, nt % NST);
        asm volatile("cp.async.commit_group;" ::: "memory");
        compute(t % NST);
    }

    #pragma unroll
    for (int mi = 0; mi < 4; mi++) {
        #pragma unroll
        for (int ni = 0; ni < 8; ni++) {
            const int r0 = blockIdx.y * 128 + warpM * 64 + mi * 16 + g;
            const int c0 = blockIdx.x * 128 + warpN * 64 + ni * 8 + 2 * tig;
            #pragma unroll
            for (int hh = 0; hh < 2; hh++) {
                float v0 = acc[mi][ni][hh * 2 + 0];
                float v1 = acc[mi][ni][hh * 2 + 1];
                if (MODE == 1) {
                    if (c0 < 2 * CH)     v0 = (v0 > 0.f) ? (v0 + 1.f) : expf(v0);
                    if (c0 + 1 < 2 * CH) v1 = (v1 > 0.f) ? (v1 + 1.f) : expf(v1);
                    __half2 p = __floats2half2_rn(v0, v1);
                    *(__half2*)((__half*)Cv + (size_t)(r0 + hh * 8) * Ncols + c0) = p;
                } else {
                    v0 += bias[c0]; v1 += bias[c0 + 1];
                    *(float2*)((float*)Cv + (size_t)(r0 + hh * 8) * Ncols + c0) =
                        make_float2(v0, v1);
                }
            }
        }
    }
}

// ================= prep: fp32 -> fp16 (rn) =================================
__global__ __launch_bounds__(256)
void cvt_f16_kernel(const float4* __restrict__ in, uint4* __restrict__ outp, int n8)
{
    int i = blockIdx.x * 256 + threadIdx.x;
    if (i < n8) {
        float4 a = in[2 * i], b = in[2 * i + 1];
        __half2 h0 = __floats2half2_rn(a.x, a.y);
        __half2 h1 = __floats2half2_rn(a.z, a.w);
        __half2 h2 = __floats2half2_rn(b.x, b.y);
        __half2 h3 = __floats2half2_rn(b.z, b.w);
        uint4 o;
        o.x = *reinterpret_cast<uint32_t*>(&h0);
        o.y = *reinterpret_cast<uint32_t*>(&h1);
        o.z = *reinterpret_cast<uint32_t*>(&h2);
        o.w = *reinterpret_cast<uint32_t*>(&h3);
        outp[i] = o;
    }
}

// ===== kv via tensor cores: kv[d,e] = sum_n k[n,d] v[n,e]; + sumk ==========
// grid (BH, KVCHUNKS), 128 threads = 4 warps. Per block: M=64(d), N=64(e),
// K=512(n). Warp w: rows d = w*16..+15, all 64 e. A = k^T via ldmatrix.trans.
__global__ __launch_bounds__(128)
void kv_mma_kernel()
{
    __shared__ __align__(16) __half ks[32 * 64];   // [n][d], swizzled
    __shared__ __align__(16) __half vs[32 * 64];   // [n][e], swizzled
    __shared__ float red[2][64];

    const int tid  = threadIdx.x;
    const int lane = tid & 31;
    const int warp = tid >> 5;
    const int bh   = blockIdx.x;
    const int chunk = blockIdx.y;
    const int b = bh / HEADS, h = bh % HEADS;

    const __half* base = g_qkvh + (size_t)b * SEQ * QKVC + h * HD;
    const int nBeg = chunk * (SEQ / KVCHUNKS);
    const int nEnd = nBeg + (SEQ / KVCHUNKS);

    const uint32_t kb = smem_u32(ks);
    const uint32_t vb = smem_u32(vs);

    float acc[8][4];
    #pragma unroll
    for (int j = 0; j < 8; j++)
        #pragma unroll
        for (int l = 0; l < 4; l++) acc[j][l] = 0.f;

    // sumk: thread sums column (tid&63) over row group (tid>>6)*16..+15
    const int scol = tid & 63;
    const int srow0 = (tid >> 6) * 16;
    float ssum = 0.f;
    const uint32_t s_addr_base = kb + ((scol >> 3) << 4);   // chunk part (pre-XOR)
    const int s_in = (scol & 7) * 2;

    // A fragment address (k^T): lanes {0-7,8-15,16-23,24-31} ->
    //   (rows n0-7,col d0),(n0-7,d0+8),(n8-15,d0),(n8-15,d0+8)
    const int d0 = warp * 16;
    const int a_nrow = (lane & 7) + ((lane >> 4) << 3);    // + ks*16
    const int a_dcol = d0 + (lane & 8);                    // d0 or d0+8
    const int a_chunk = a_dcol >> 3;

    // B fragment (v): lanes 0-15 rows k0-15 col e0; 16-31 col e0+8
    const int b_krow = lane & 15;                          // + ks*16
    const int b_eoff = (lane >> 4) << 3;

    for (int n0 = nBeg; n0 < nEnd; n0 += 32) {
        // load k,v tiles: 32 rows x 64 halves = 256 chunks each, 2/thread
        #pragma unroll
        for (int it = 0; it < 2; it++) {
            int id = tid + it * 128;
            int r = id >> 3, c = id & 7;
            const __half* rowp = base + (size_t)(n0 + r) * QKVC;
            uint4 kq = *(const uint4*)(rowp + CH + c * 8);
            uint4 vq = *(const uint4*)(rowp + 2 * CH + c * 8);
            *(uint4*)((char*)ks + r * 128 + ((c ^ (r & 7)) << 4)) = kq;
            *(uint4*)((char*)vs + r * 128 + ((c ^ (r & 7)) << 4)) = vq;
        }
        __syncthreads();

        #pragma unroll
        for (int ksi = 0; ksi < 2; ksi++) {
            uint32_t af[4], bf[8][2];
            {
                int nr = ksi * 16 + a_nrow;
                uint32_t addr = kb + nr * 128 + (((a_chunk ^ (nr & 7))) << 4);
                asm volatile(
                    "ldmatrix.sync.aligned.m8n8.x4.trans.shared.b16 {%0,%1,%2,%3}, [%4];"
                    : "=r"(af[0]), "=r"(af[1]), "=r"(af[2]), "=r"(af[3])
                    : "r"(addr));
            }
            #pragma unroll
            for (int nip = 0; nip < 4; nip++) {
                int kk = ksi * 16 + b_krow;
                int e = nip * 16 + b_eoff;
                int c = e >> 3;
                uint32_t addr = vb + kk * 128 + (((c ^ (kk & 7))) << 4);
                asm volatile(
                    "ldmatrix.sync.aligned.m8n8.x4.trans.shared.b16 {%0,%1,%2,%3}, [%4];"
                    : "=r"(bf[2 * nip][0]), "=r"(bf[2 * nip][1]),
                      "=r"(bf[2 * nip + 1][0]), "=r"(bf[2 * nip + 1][1])
                    : "r"(addr));
            }
            #pragma unroll
            for (int ni = 0; ni < 8; ni++)
                MMA16816(acc[ni], af, bf[ni][0], bf[ni][1]);
        }

        // sumk partial over this tile (16 rows per thread)
        #pragma unroll
        for (int rr = 0; rr < 16; rr++) {
            int row = srow0 + rr;
            uint32_t a = s_addr_base;
            // swizzle: chunk ^ (row&7)
            a = kb + row * 128 + ((((scol >> 3) ^ (row & 7))) << 4) + s_in;
            __half hv;
            asm volatile("ld.shared.b16 %0, [%1];" : "=h"(*(short*)&hv) : "r"(a));
            ssum += __half2float(hv);
        }
        __syncthreads();
    }

    // write kv partials (fp32)
    const int g = lane >> 2, tig = lane & 3;
    float* kvp = g_kvp + ((size_t)chunk * BH + bh) * HD * HD;
    #pragma unroll
    for (int hh = 0; hh < 2; hh++) {
        const int dr = d0 + g + hh * 8;
        #pragma unroll
        for (int ni = 0; ni < 8; ni++) {
            const int e = ni * 8 + 2 * tig;
            *(float2*)(kvp + dr * HD + e) =
                make_float2(acc[ni][hh * 2 + 0], acc[ni][hh * 2 + 1]);
        }
    }
    red[tid >> 6][scol] = ssum;
    __syncthreads();
    if (tid < HD)
        g_sumkp[((size_t)chunk * BH + bh) * HD + tid] = red[0][tid] + red[1][tid];
}

__global__ __launch_bounds__(256)
void kv_reduce_kernel()
{
    const int bh = blockIdx.x;
    const int tid = threadIdx.x;
    for (int i = tid; i < HD * HD; i += 256) {
        float s = 0.f;
        #pragma unroll
        for (int c = 0; c < KVCHUNKS; c++)
            s += g_kvp[((size_t)c * BH + bh) * HD * HD + i];
        g_kvh[(size_t)bh * HD * HD + i] = __float2half_rn(s);
    }
    if (tid < HD) {
        float s = 0.f;
        #pragma unroll
        for (int c = 0; c < KVCHUNKS; c++)
            s += g_sumkp[((size_t)c * BH + bh) * HD + tid];
        g_sumk[(size_t)bh * HD + tid] = s;
    }
}

// ================= y via tensor cores: y = (q @ kv) / (q . sumk) ===========
__global__ __launch_bounds__(128)
void y_mma_kernel()
{
    __shared__ __align__(16) __half qs[128 * 64];
    __shared__ __align__(16) __half kvs[64 * 64];
    __shared__ float sumkS[HD];
    __shared__ float denomS[128];

    const int tid  = threadIdx.x;
    const int lane = tid & 31;
    const int warp = tid >> 5;
    const int bh   = blockIdx.y;
    const int b    = bh / HEADS, h = bh % HEADS;
    const int n0   = blockIdx.x * 128;

    const __half* qg = g_qkvh + ((size_t)b * SEQ + n0) * QKVC + h * HD;

    #pragma unroll
    for (int it = 0; it < 8; it++) {
        int id = tid + it * 128;
        int r = id >> 3, c = id & 7;
        uint4 o = *(const uint4*)(qg + (size_t)r * QKVC + c * 8);
        *(uint4*)((char*)qs + r * 128 + (((c ^ (r & 7))) << 4)) = o;
    }
    const __half* kvg = g_kvh + (size_t)bh * HD * HD;
    #pragma unroll
    for (int it = 0; it < 4; it++) {
        int id = tid + it * 128;
        int d = id >> 3, c = id & 7;
        uint4 o = *(const uint4*)(kvg + d * HD + c * 8);
        *(uint4*)((char*)kvs + d * 128 + (((c ^ (d & 7))) << 4)) = o;
    }
    if (tid < HD) sumkS[tid] = g_sumk[(size_t)bh * HD + tid];
    __syncthreads();

    {
        const __half* qr = qg + (size_t)tid * QKVC;
        float s = 0.f;
        #pragma unroll
        for (int d = 0; d < HD; d += 8) {
            uint4 v = *(const uint4*)(qr + d);
            const __half2* hp = (const __half2*)&v;
            #pragma unroll
            for (int j = 0; j < 4; j++) {
                float2 f = __half22float2(hp[j]);
                s += f.x * sumkS[d + 2 * j] + f.y * sumkS[d + 2 * j + 1];
            }
        }
        denomS[tid] = 1.0f / s;
    }

    const uint32_t qb = smem_u32(qs);
    const uint32_t kb = smem_u32(kvs);

    float acc[2][8][4];
    #pragma unroll
    for (int i = 0; i < 2; i++)
        #pragma unroll
        for (int j = 0; j < 8; j++)
            #pragma unroll
            for (int l = 0; l < 4; l++) acc[i][j][l] = 0.f;

    #pragma unroll
    for (int ks = 0; ks < 4; ks++) {
        uint32_t af[2][4], bf[8][2];
        #pragma unroll
        for (int mi = 0; mi < 2; mi++) {
            int r = warp * 32 + mi * 16 + (lane & 15);
            int k = ks * 16 + ((lane >> 4) << 3);
            int c = k >> 3;
            uint32_t addr = qb + r * 128 + (((c ^ (r & 7))) << 4);
            asm volatile(
                "ldmatrix.sync.aligned.m8n8.x4.shared.b16 {%0,%1,%2,%3}, [%4];"
                : "=r"(af[mi][0]), "=r"(af[mi][1]), "=r"(af[mi][2]), "=r"(af[mi][3])
                : "r"(addr));
        }
        #pragma unroll
        for (int nip = 0; nip < 4; nip++) {
            int k = ks * 16 + (lane & 15);
            int n = nip * 16 + ((lane >> 4) << 3);
            int c = n >> 3;
            uint32_t addr = kb + k * 128 + (((c ^ (k & 7))) << 4);
            asm volatile(
                "ldmatrix.sync.aligned.m8n8.x4.trans.shared.b16 {%0,%1,%2,%3}, [%4];"
                : "=r"(bf[2 * nip][0]), "=r"(bf[2 * nip][1]),
                  "=r"(bf[2 * nip + 1][0]), "=r"(bf[2 * nip + 1][1])
                : "r"(addr));
        }
        #pragma unroll
        for (int mi = 0; mi < 2; mi++)
            #pragma unroll
            for (int ni = 0; ni < 8; ni++)
                MMA16816(acc[mi][ni], af[mi], bf[ni][0], bf[ni][1]);
    }

    __syncwarp();

    const int g = lane >> 2, tig = lane & 3;
    #pragma unroll
    for (int mi = 0; mi < 2; mi++) {
        #pragma unroll
        for (int hh = 0; hh < 2; hh++) {
            const int rl = warp * 32 + mi * 16 + g + hh * 8;
            const float inv = denomS[rl];
            __half* yrow = g_yh + ((size_t)b * SEQ + n0 + rl) * CH + h * HD;
            #pragma unroll
            for (int ni = 0; ni < 8; ni++) {
                const int col = ni * 8 + 2 * tig;
                __half2 p = __floats2half2_rn(acc[mi][ni][hh * 2 + 0] * inv,
                                              acc[mi][ni][hh * 2 + 1] * inv);
                *(__half2*)(yrow + col) = p;
            }
        }
    }
}

// ---------------------------------------------------------------------------
extern "C" void kernel_launch(void* const* d_in, const int* in_sizes, int n_in,
                              void* d_out, int out_size)
{
    const float* x      = (const float*)d_in[0];
    const float* w_qkv  = (const float*)d_in[1];
    const float* w_proj = (const float*)d_in[2];
    const float* b_proj = (const float*)d_in[3];
    float* out = (float*)d_out;

    __half *qkvh_p, *xh_p, *wqkvh_p, *wprojh_p, *yh_p;
    cudaGetSymbolAddress((void**)&qkvh_p,   g_qkvh);
    cudaGetSymbolAddress((void**)&xh_p,     g_xh);
    cudaGetSymbolAddress((void**)&wqkvh_p,  g_wqkvh);
    cudaGetSymbolAddress((void**)&wprojh_p, g_wprojh);
    cudaGetSymbolAddress((void**)&yh_p,     g_yh);

    cudaFuncSetAttribute(hgemm<1>, cudaFuncAttributeMaxDynamicSharedMemorySize, HG_SMEM);
    cudaFuncSetAttribute(hgemm<2>, cudaFuncAttributeMaxDynamicSharedMemorySize, HG_SMEM);

    // 0) convert inputs to fp16 (rn)
    cvt_f16_kernel<<<(ROWS * CH / 8 + 255) / 256, 256>>>(
        (const float4*)x, (uint4*)xh_p, ROWS * CH / 8);
    cvt_f16_kernel<<<(CH * QKVC / 8 + 255) / 256, 256>>>(
        (const float4*)w_qkv, (uint4*)wqkvh_p, CH * QKVC / 8);
    cvt_f16_kernel<<<(CH * CH / 8 + 255) / 256, 256>>>(
        (const float4*)w_proj, (uint4*)wprojh_p, CH * CH / 8);

    // 1) qkv = x @ w_qkv (fp16 TC), elu+1 fused, fp16 out
    {
        dim3 grid(QKVC / 128, ROWS / 128);
        hgemm<1><<<grid, 128, HG_SMEM>>>(xh_p, wqkvh_p, nullptr, qkvh_p, QKVC, CH);
    }
    // 2) kv outer product on tensor cores (seq-split) + reduce
    {
        dim3 grid(BH, KVCHUNKS);
        kv_mma_kernel<<<grid, 128>>>();
        kv_reduce_kernel<<<BH, 256>>>();
    }
    // 3) y = (q @ kv) / (q . sumk) on tensor cores, fp16 out
    {
        dim3 grid(SEQ / 128, BH);
        y_mma_kernel<<<grid, 128>>>();
    }
    // 4) out = y @ w_proj + b_proj (fp16 TC, fp32 out)
    {
        dim3 grid(CH / 128, ROWS / 128);
        hgemm<2><<<grid, 128, HG_SMEM>>>(yh_p, wprojh_p, b_proj, out, CH, CH);
    }
}